// round 5
// baseline (speedup 1.0000x reference)
#include <cuda_runtime.h>
#include <cuda_bf16.h>
#include <cstdint>

// ---------------- problem constants ----------------
#define BATCH 64
#define DCH   512
#define CIN   2304
#define HWP   196
#define NTOT  (BATCH * HWP)        // 12544
#define CHW   (DCH * HWP)          // 100352
#define QO    (BATCH * CHW)        // elems per q/k/v tensor (= NTOT*512)

// ---------------- scratch (static device memory) ----------------
__device__ float4 g_xT_hi [(64*196*2304)/8];
__device__ float4 g_xT_lo [(64*196*2304)/8];
__device__ float4 g_wr_hi [(512*2304)/8];
__device__ float4 g_wr_lo [(512*2304)/8];
__device__ float4 g_wqkv_hi[(3*512*4608)/8];
__device__ float4 g_wqkv_lo[(3*512*4608)/8];
__device__ float4 g_wc_hi [(512*4608)/8];
__device__ float4 g_wc_lo [(512*4608)/8];
__device__ float4 g_xrT_hi[(BATCH*CHW)/8];
__device__ float4 g_xrT_lo[(BATCH*CHW)/8];
__device__ float4 g_qkv   [(3*BATCH*CHW)/4];   // qT,kT,vT fp32 [n][512]
__device__ float4 g_att   [(HWP*BATCH*BATCH)/4]; // [p][i][j]
__device__ float4 g_virt  [(BATCH*CHW)/4];     // virtT fp32 [n][512]
__device__ float4 g_vT_hi [(BATCH*CHW)/8];
__device__ float4 g_vT_lo [(BATCH*CHW)/8];
__device__ float4 g_co    [(BATCH*CHW)/4];     // coT fp32 [n][512]
__device__ float  g_stats [2*BATCH];

// ---------------- helpers ----------------
__device__ __forceinline__ uint32_t smem_to_u32(const void* p) {
    uint32_t a;
    asm("{ .reg .u64 t; cvta.to.shared.u64 t, %1; cvt.u32.u64 %0, t; }" : "=r"(a) : "l"(p));
    return a;
}
#define CP_ASYNC16(dst, src, sz) \
    asm volatile("cp.async.cg.shared.global [%0], [%1], 16, %2;" \
                 :: "r"(dst), "l"(src), "r"(sz) : "memory")
#define CP_COMMIT() asm volatile("cp.async.commit_group;" ::: "memory")
#define CP_WAIT2()  asm volatile("cp.async.wait_group 2;" ::: "memory")
#define CP_WAIT0()  asm volatile("cp.async.wait_group 0;" ::: "memory")

#define LDMATRIX_X4(r0, r1, r2, r3, addr) \
    asm volatile("ldmatrix.sync.aligned.m8n8.x4.shared.b16 {%0,%1,%2,%3}, [%4];" \
                 : "=r"(r0), "=r"(r1), "=r"(r2), "=r"(r3) : "r"(addr))

#define MMA16816(d, a0, a1, a2, a3, b0, b1) \
    asm volatile("mma.sync.aligned.m16n8k16.row.col.f32.bf16.bf16.f32 " \
                 "{%0,%1,%2,%3}, {%4,%5,%6,%7}, {%8,%9}, {%0,%1,%2,%3};" \
                 : "+f"((d)[0]), "+f"((d)[1]), "+f"((d)[2]), "+f"((d)[3]) \
                 : "r"(a0), "r"(a1), "r"(a2), "r"(a3), "r"(b0), "r"(b1))

// smem tile rows of 32 bf16 (64B); 16B slots XOR-swizzled by (row>>1)&3
__device__ __forceinline__ uint32_t swz(int row, int slot) {
    return (uint32_t)row * 64u + (uint32_t)((slot ^ ((row >> 1) & 3)) << 4);
}

// ---------------- unified split-bf16 GEMM ----------------
// D = A*B fp32 via hi*hi + hi*lo + lo*hi, all three per K-chunk residency.
// MODE 0: KTOT=2304, CB=2304 (1x1 reduce). MODE 1: KTOT=4608 (k=tap*512+c), CB=512.
// OUTM 0: write bf16 hi/lo transposed [n][c]. OUTM 1: write fp32 transposed [n][512],
//         tensor s = m0>>9 (fused qkv).
// Stage: Ahi 8KB | Alo 8KB | Bhi 16KB | Blo 16KB = 48KB; 4 stages.
#define STAGE_BYTES 49152
#define GEMM_SMEM   (4 * STAGE_BYTES)

template<int MODE, int OUTM>
__global__ __launch_bounds__(256, 1)
void gemm_mma(const __nv_bfloat16* __restrict__ Ahi, const __nv_bfloat16* __restrict__ Alo,
              const __nv_bfloat16* __restrict__ Bhi, const __nv_bfloat16* __restrict__ Blo,
              float* __restrict__ Of,
              __nv_bfloat16* __restrict__ Ohi, __nv_bfloat16* __restrict__ Olo)
{
    constexpr int KTOT = MODE ? 4608 : 2304;
    constexpr int CB   = MODE ? 512  : 2304;
    constexpr int NCHK = KTOT / 32;

    extern __shared__ char smem[];
    const uint32_t sb = smem_to_u32(smem);

    const int t    = threadIdx.x;
    const int lane = t & 31;
    const int wid  = t >> 5;
    const int m0   = blockIdx.x * 128;
    const int n0   = blockIdx.y * 256;

    // ---- load assignments ----
    const int slot  = t & 3;
    const int lrow0 = t >> 2;

    int aoff[2];
    uint32_t adst[2];
#pragma unroll
    for (int i = 0; i < 2; i++) {
        const int r = lrow0 + 64 * i;
        aoff[i] = (m0 + r) * KTOT + slot * 8;
        adst[i] = swz(r, slot);
    }
    int bbase[4], bpy[4], bpx[4];
    uint32_t bdst[4];
#pragma unroll
    for (int i = 0; i < 4; i++) {
        const int r = lrow0 + 64 * i;
        const int n = n0 + r;
        const int b = n / HWP;
        const int p = n - b * HWP;
        bbase[i] = n * CB;
        bpy[i] = p / 14;
        bpx[i] = p - bpy[i] * 14;
        bdst[i] = swz(r, slot);
    }

    auto issue = [&](int chunk, int buf) {
        const uint32_t st = sb + (uint32_t)buf * STAGE_BYTES;
        int kbase, doff, dy = 0, dx = 0;
        if (MODE) {
            const int tap = chunk >> 4;
            const int c0  = (chunk & 15) * 32;
            kbase = tap * 512 + c0;
            dy = tap / 3 - 1;
            dx = tap - (tap / 3) * 3 - 1;
            doff = (dy * 14 + dx) * CB + c0;
        } else {
            kbase = chunk * 32;
            doff  = kbase;
        }
#pragma unroll
        for (int i = 0; i < 2; i++) {
            CP_ASYNC16(st + adst[i],         Ahi + aoff[i] + kbase, 16u);
            CP_ASYNC16(st + 8192u + adst[i], Alo + aoff[i] + kbase, 16u);
        }
#pragma unroll
        for (int i = 0; i < 4; i++) {
            uint32_t sz = 16u;
            long off = (long)bbase[i] + doff + slot * 8;
            if (MODE) {
                const bool ok = ((unsigned)(bpy[i] + dy) < 14u) &&
                                ((unsigned)(bpx[i] + dx) < 14u);
                if (!ok) { sz = 0u; off = 0; }
            }
            CP_ASYNC16(st + 16384u + bdst[i], Bhi + off, sz);
            CP_ASYNC16(st + 32768u + bdst[i], Blo + off, sz);
        }
        CP_COMMIT();
    };

    // ---- per-warp fragment addresses ----
    const int wm = (wid & 1) * 64;
    const int wn = (wid >> 1) * 64;
    uint32_t addrA[4][2], addrB[4][2];
#pragma unroll
    for (int mi = 0; mi < 4; mi++) {
        const int row = wm + mi * 16 + (lane & 15);
#pragma unroll
        for (int kh = 0; kh < 2; kh++)
            addrA[mi][kh] = swz(row, kh * 2 + (lane >> 4));
    }
#pragma unroll
    for (int nb = 0; nb < 4; nb++) {
        const int row = wn + nb * 16 + (lane & 7) + ((lane & 16) ? 8 : 0);
#pragma unroll
        for (int kh = 0; kh < 2; kh++)
            addrB[nb][kh] = swz(row, kh * 2 + ((lane >> 3) & 1));
    }

    float acc[4][8][4];
#pragma unroll
    for (int mi = 0; mi < 4; mi++)
#pragma unroll
        for (int ni = 0; ni < 8; ni++)
#pragma unroll
            for (int r = 0; r < 4; r++) acc[mi][ni][r] = 0.0f;

    issue(0, 0);
    issue(1, 1);
    issue(2, 2);

    for (int it = 0; it < NCHK; ++it) {
        CP_WAIT2();
        __syncthreads();
        if (it + 3 < NCHK) issue(it + 3, (it + 3) & 3);
        else CP_COMMIT();

        const uint32_t st = sb + (uint32_t)(it & 3) * STAGE_BYTES;
        const uint32_t sAhi = st, sAlo = st + 8192u, sBhi = st + 16384u, sBlo = st + 32768u;
#pragma unroll
        for (int kh = 0; kh < 2; kh++) {
            uint32_t ah[4][4], bh[8][2];
#pragma unroll
            for (int mi = 0; mi < 4; mi++)
                LDMATRIX_X4(ah[mi][0], ah[mi][1], ah[mi][2], ah[mi][3], sAhi + addrA[mi][kh]);
#pragma unroll
            for (int nb = 0; nb < 4; nb++) {
                uint32_t r0, r1, r2, r3;
                LDMATRIX_X4(r0, r1, r2, r3, sBhi + addrB[nb][kh]);
                bh[2 * nb][0] = r0; bh[2 * nb][1] = r1;
                bh[2 * nb + 1][0] = r2; bh[2 * nb + 1][1] = r3;
            }
#pragma unroll
            for (int mi = 0; mi < 4; mi++)
#pragma unroll
                for (int ni = 0; ni < 8; ni++)
                    MMA16816(acc[mi][ni], ah[mi][0], ah[mi][1], ah[mi][2], ah[mi][3],
                             bh[ni][0], bh[ni][1]);
            // hi * lo
            uint32_t bl[8][2];
#pragma unroll
            for (int nb = 0; nb < 4; nb++) {
                uint32_t r0, r1, r2, r3;
                LDMATRIX_X4(r0, r1, r2, r3, sBlo + addrB[nb][kh]);
                bl[2 * nb][0] = r0; bl[2 * nb][1] = r1;
                bl[2 * nb + 1][0] = r2; bl[2 * nb + 1][1] = r3;
            }
#pragma unroll
            for (int mi = 0; mi < 4; mi++)
#pragma unroll
                for (int ni = 0; ni < 8; ni++)
                    MMA16816(acc[mi][ni], ah[mi][0], ah[mi][1], ah[mi][2], ah[mi][3],
                             bl[ni][0], bl[ni][1]);
            // lo * hi
            uint32_t al[4][4];
#pragma unroll
            for (int mi = 0; mi < 4; mi++)
                LDMATRIX_X4(al[mi][0], al[mi][1], al[mi][2], al[mi][3], sAlo + addrA[mi][kh]);
#pragma unroll
            for (int mi = 0; mi < 4; mi++)
#pragma unroll
                for (int ni = 0; ni < 8; ni++)
                    MMA16816(acc[mi][ni], al[mi][0], al[mi][1], al[mi][2], al[mi][3],
                             bh[ni][0], bh[ni][1]);
        }
    }

    CP_WAIT0();
    __syncthreads();

    // ---- transposed epilogue: slabs of 32 n through smem, coalesced [n][c] writes ----
    float* smf = (float*)smem;                  // [32][132]
    const int s_tensor = m0 >> 9;
    const int cbase = m0 & 511;
    for (int slab = 0; slab < 8; ++slab) {
        __syncthreads();
        if ((slab >> 1) == (wn >> 6)) {
            const int nsub = (slab & 1) * 32;
#pragma unroll
            for (int ni4 = 0; ni4 < 4; ni4++) {
                const int ni = (nsub >> 3) + ni4;
                const int nl = ni * 8 + (lane & 3) * 2 - nsub;
                const int r0 = wm + (lane >> 2);
#pragma unroll
                for (int mi = 0; mi < 4; mi++) {
                    const int m = r0 + mi * 16;
                    smf[nl * 132 + m]           = acc[mi][ni][0];
                    smf[(nl + 1) * 132 + m]     = acc[mi][ni][1];
                    smf[nl * 132 + m + 8]       = acc[mi][ni][2];
                    smf[(nl + 1) * 132 + m + 8] = acc[mi][ni][3];
                }
            }
        }
        __syncthreads();
        const int nloc = t >> 3;
        const int c16  = (t & 7) * 16;
        const long ng  = n0 + slab * 32 + nloc;
        float vals[16];
#pragma unroll
        for (int j = 0; j < 16; j++) vals[j] = smf[nloc * 132 + c16 + j];
        if (OUTM == 0) {
            uint32_t hw[8], lw[8];
#pragma unroll
            for (int j = 0; j < 8; j++) {
                float v0 = vals[2 * j], v1 = vals[2 * j + 1];
                __nv_bfloat162 hp = __float22bfloat162_rn(make_float2(v0, v1));
                float r0 = v0 - __bfloat162float(__low2bfloat16(hp));
                float r1 = v1 - __bfloat162float(__high2bfloat16(hp));
                __nv_bfloat162 lp = __float22bfloat162_rn(make_float2(r0, r1));
                hw[j] = *(uint32_t*)&hp;
                lw[j] = *(uint32_t*)&lp;
            }
            uint4* ph = (uint4*)(Ohi + ng * 512 + cbase + c16);
            uint4* pl = (uint4*)(Olo + ng * 512 + cbase + c16);
            ph[0] = make_uint4(hw[0], hw[1], hw[2], hw[3]);
            ph[1] = make_uint4(hw[4], hw[5], hw[6], hw[7]);
            pl[0] = make_uint4(lw[0], lw[1], lw[2], lw[3]);
            pl[1] = make_uint4(lw[4], lw[5], lw[6], lw[7]);
        } else {
            float4* po = (float4*)(Of + (long)s_tensor * QO + ng * 512 + cbase + c16);
#pragma unroll
            for (int j = 0; j < 4; j++)
                po[j] = make_float4(vals[4 * j], vals[4 * j + 1], vals[4 * j + 2], vals[4 * j + 3]);
        }
    }
}

// ---------------- conversion kernels ----------------
__global__ __launch_bounds__(256)
void conv_split(const float* __restrict__ in, __nv_bfloat16* __restrict__ hi,
                __nv_bfloat16* __restrict__ lo, int n)
{
    const int i = blockIdx.x * 256 + threadIdx.x;
    if (i >= n) return;
    const float v = in[i];
    const __nv_bfloat16 h = __float2bfloat16(v);
    hi[i] = h;
    lo[i] = __float2bfloat16(v - __bfloat162float(h));
}

__global__ __launch_bounds__(256)
void conv_wqkv(const float* __restrict__ wq, const float* __restrict__ wk,
               const float* __restrict__ wv,
               __nv_bfloat16* __restrict__ hi, __nv_bfloat16* __restrict__ lo)
{
    const int i = blockIdx.x * 256 + threadIdx.x;
    if (i >= 3 * 512 * 4608) return;
    const int s = i / (512 * 4608);
    const int r = i - s * (512 * 4608);
    const int m = r / 4608;
    const int k = r - m * 4608;
    const int kk = k >> 9;
    const int c = k & 511;
    const float* w = (s == 0) ? wq : ((s == 1) ? wk : wv);
    const float v = w[(m * 512 + c) * 9 + kk];
    const __nv_bfloat16 h = __float2bfloat16(v);
    hi[i] = h;
    lo[i] = __float2bfloat16(v - __bfloat162float(h));
}

__global__ __launch_bounds__(256)
void conv_wc(const float* __restrict__ w,
             __nv_bfloat16* __restrict__ hi, __nv_bfloat16* __restrict__ lo)
{
    const int i = blockIdx.x * 256 + threadIdx.x;
    if (i >= 512 * 4608) return;
    const int m = i / 4608;
    const int k = i - m * 4608;
    const int kk = k >> 9;
    const int c = k & 511;
    const float v = w[(m * 512 + c) * 9 + kk];
    const __nv_bfloat16 h = __float2bfloat16(v);
    hi[i] = h;
    lo[i] = __float2bfloat16(v - __bfloat162float(h));
}

// x [b][2304][196] fp32 -> xT [b*196+p][2304] bf16 hi/lo
__global__ __launch_bounds__(256)
void tconv(const float* __restrict__ in, __nv_bfloat16* __restrict__ hi,
           __nv_bfloat16* __restrict__ lo, int C)
{
    __shared__ float tile[32][33];
    const int b = blockIdx.z;
    const int c0 = blockIdx.y * 32;
    const int p0 = blockIdx.x * 32;
    const int tx = threadIdx.x, ty = threadIdx.y;
    const float* src = in + ((long)b * C + c0) * HWP;
    const int p = p0 + tx;
    for (int i = ty; i < 32; i += 8)
        tile[i][tx] = (p < HWP) ? src[i * HWP + p] : 0.0f;
    __syncthreads();
    for (int i = ty; i < 32; i += 8) {
        const int pp = p0 + i;
        if (pp < HWP) {
            const float v = tile[tx][i];
            const __nv_bfloat16 h = __float2bfloat16(v);
            const long o = ((long)b * HWP + pp) * C + c0 + tx;
            hi[o] = h;
            lo[o] = __float2bfloat16(v - __bfloat162float(h));
        }
    }
}

// ---------------- attention on transposed [n][512] fp32 ----------------
// att[p][i][j] = <q_i, k_j>(p) / sqrt(512)
__global__ __launch_bounds__(256)
void attn_scores(const float* __restrict__ Q, const float* __restrict__ Kin, float* __restrict__ A)
{
    const int p = blockIdx.x;
    const int t = threadIdx.x;
    __shared__ float qs[64][33];
    __shared__ float ks[64][33];
    float acc[4][4];
#pragma unroll
    for (int a = 0; a < 4; a++)
#pragma unroll
        for (int b4 = 0; b4 < 4; b4++) acc[a][b4] = 0.0f;
    const int ti = (t & 15) * 4;
    const int tj = (t >> 4) * 4;
    for (int ch = 0; ch < 16; ++ch) {
        const int c0 = ch * 32;
        __syncthreads();
        for (int e = t; e < 64 * 32; e += 256) {
            const int i = e >> 5, c = e & 31;
            qs[i][c] = Q[((long)i * HWP + p) * 512 + c0 + c];
            ks[i][c] = Kin[((long)i * HWP + p) * 512 + c0 + c];
        }
        __syncthreads();
#pragma unroll 8
        for (int c = 0; c < 32; ++c) {
            float qa[4], kb[4];
#pragma unroll
            for (int a = 0; a < 4; a++) qa[a] = qs[ti + a][c];
#pragma unroll
            for (int b4 = 0; b4 < 4; b4++) kb[b4] = ks[tj + b4][c];
#pragma unroll
            for (int a = 0; a < 4; a++)
#pragma unroll
                for (int b4 = 0; b4 < 4; b4++) acc[a][b4] = fmaf(qa[a], kb[b4], acc[a][b4]);
        }
    }
    const float scale = 0.044194173824159216f;
    float* Ab = A + (long)p * 4096;
#pragma unroll
    for (int a = 0; a < 4; a++)
#pragma unroll
        for (int b4 = 0; b4 < 4; b4++)
            Ab[(ti + a) * 64 + tj + b4] = acc[a][b4] * scale;
}

// softmax over j for each (p, i): one warp per row, contiguous 64 floats
__global__ __launch_bounds__(256)
void softmax_j(float* __restrict__ A)
{
    const int gw   = (blockIdx.x * blockDim.x + threadIdx.x) >> 5;
    const int lane = threadIdx.x & 31;
    if (gw >= HWP * BATCH) return;
    float* row = A + (long)gw * 64;
    float v0 = row[lane];
    float v1 = row[lane + 32];
    float m = fmaxf(v0, v1);
#pragma unroll
    for (int o = 16; o > 0; o >>= 1) m = fmaxf(m, __shfl_xor_sync(0xffffffffu, m, o));
    float e0 = __expf(v0 - m);
    float e1 = __expf(v1 - m);
    float ssum = e0 + e1;
#pragma unroll
    for (int o = 16; o > 0; o >>= 1) ssum += __shfl_xor_sync(0xffffffffu, ssum, o);
    const float inv = 1.0f / ssum;
    row[lane]      = e0 * inv;
    row[lane + 32] = e1 * inv;
}

// virtT[(i*196+p)*512 + c] = sum_j att[p][i][j] * vT[(j*196+p)*512 + c]
__global__ __launch_bounds__(256)
void attn_apply(const float* __restrict__ A, const float* __restrict__ V, float* __restrict__ Out)
{
    const int p = blockIdx.x;
    const int t = threadIdx.x;
    __shared__ float as[64][65];
    __shared__ float vs[64][33];
    const float* Ab = A + (long)p * 4096;
    for (int e = t; e < 64 * 64; e += 256) {
        const int i = e >> 6, j = e & 63;
        as[i][j] = Ab[i * 64 + j];
    }
    __syncthreads();
    const int ti = (t & 15) * 4;
    const int tc = (t >> 4) * 2;
    for (int ch = 0; ch < 16; ++ch) {
        const int c0 = ch * 32;
        if (ch) __syncthreads();
        for (int e = t; e < 64 * 32; e += 256) {
            const int j = e >> 5, c = e & 31;
            vs[j][c] = V[((long)j * HWP + p) * 512 + c0 + c];
        }
        __syncthreads();
        float acc[4][2];
#pragma unroll
        for (int a = 0; a < 4; a++) { acc[a][0] = 0.0f; acc[a][1] = 0.0f; }
#pragma unroll 8
        for (int j = 0; j < 64; ++j) {
            float vv0 = vs[j][tc];
            float vv1 = vs[j][tc + 1];
#pragma unroll
            for (int a = 0; a < 4; a++) {
                const float av = as[ti + a][j];
                acc[a][0] = fmaf(av, vv0, acc[a][0]);
                acc[a][1] = fmaf(av, vv1, acc[a][1]);
            }
        }
#pragma unroll
        for (int a = 0; a < 4; a++)
            *(float2*)(Out + ((long)(ti + a) * HWP + p) * 512 + c0 + tc) =
                make_float2(acc[a][0], acc[a][1]);
    }
}

// ---------------- GroupNorm stats (virtT contiguous per batch) ----------------
__global__ __launch_bounds__(256)
void gn_stats(const float* __restrict__ Vt, float* __restrict__ stats)
{
    const int i = blockIdx.x;
    const int t = threadIdx.x;
    float s = 0.0f, s2 = 0.0f;
    const float* row = Vt + (long)i * CHW;
    for (int e = t; e < CHW; e += 256) {
        const float v = row[e];
        s += v;
        s2 = fmaf(v, v, s2);
    }
    __shared__ float sh1[256];
    __shared__ float sh2[256];
    sh1[t] = s; sh2[t] = s2;
    __syncthreads();
    for (int st = 128; st > 0; st >>= 1) {
        if (t < st) { sh1[t] += sh1[t + st]; sh2[t] += sh2[t + st]; }
        __syncthreads();
    }
    if (t == 0) {
        const float inv_n = 1.0f / (float)CHW;
        const float mean = sh1[0] * inv_n;
        const float var  = sh2[0] * inv_n - mean * mean;
        stats[2 * i]     = mean;
        stats[2 * i + 1] = rsqrtf(var + 1e-5f);
    }
}

// fused: normalize + affine + relu + bf16 split -> vT_hi/lo [n][512]
__global__ __launch_bounds__(256)
void gn_split(const float* __restrict__ Vt, const float* __restrict__ stats,
              const float* __restrict__ gamma, const float* __restrict__ beta,
              __nv_bfloat16* __restrict__ hi, __nv_bfloat16* __restrict__ lo)
{
    const long idx = (long)blockIdx.x * 256 + threadIdx.x;
    if (idx >= (long)BATCH * CHW) return;
    const int i = (int)(idx / CHW);
    const int c = (int)(idx & 511);
    const float mean = stats[2 * i];
    const float rstd = stats[2 * i + 1];
    float v = (Vt[idx] - mean) * rstd * gamma[c] + beta[c];
    v = fmaxf(v, 0.0f);
    const __nv_bfloat16 h = __float2bfloat16(v);
    hi[idx] = h;
    lo[idx] = __float2bfloat16(v - __bfloat162float(h));
}

// residual (xrT hi+lo) + coT, avg pool over p, dot with w_pred
__global__ __launch_bounds__(256)
void pool_pred(const __nv_bfloat16* __restrict__ Xh, const __nv_bfloat16* __restrict__ Xl,
               const float* __restrict__ CO, const float* __restrict__ Wp,
               float* __restrict__ out)
{
    const int b = blockIdx.x;
    const int t = threadIdx.x;
    float acc = 0.0f;
    const long base = (long)b * CHW;
    for (int e = t; e < CHW; e += 256) {
        const int c = e & 511;
        const float xv = __bfloat162float(Xh[base + e]) + __bfloat162float(Xl[base + e]);
        acc = fmaf(Wp[c], xv + CO[base + e], acc);
    }
    __shared__ float sh[256];
    sh[t] = acc;
    __syncthreads();
    for (int st = 128; st > 0; st >>= 1) {
        if (t < st) sh[t] += sh[t + st];
        __syncthreads();
    }
    if (t == 0) out[b] = sh[0] * (1.0f / (float)HWP);
}

// ---------------- launcher ----------------
extern "C" void kernel_launch(void* const* d_in, const int* in_sizes, int n_in,
                              void* d_out, int out_size)
{
    const float* x        = (const float*)d_in[0];
    const float* w_reduce = (const float*)d_in[1];
    const float* w_q      = (const float*)d_in[2];
    const float* w_k      = (const float*)d_in[3];
    const float* w_v      = (const float*)d_in[4];
    const float* w_conv   = (const float*)d_in[5];
    const float* gamma    = (const float*)d_in[6];
    const float* beta     = (const float*)d_in[7];
    const float* w_pred   = (const float*)d_in[8];
    float* out = (float*)d_out;

    cudaFuncSetAttribute(gemm_mma<0, 0>, cudaFuncAttributeMaxDynamicSharedMemorySize, GEMM_SMEM);
    cudaFuncSetAttribute(gemm_mma<1, 1>, cudaFuncAttributeMaxDynamicSharedMemorySize, GEMM_SMEM);

    __nv_bfloat16 *xT_hi, *xT_lo, *wr_hi, *wr_lo, *wqkv_hi, *wqkv_lo, *wc_hi, *wc_lo;
    __nv_bfloat16 *xrT_hi, *xrT_lo, *vT_hi, *vT_lo;
    float *qkv, *att, *virt, *co, *stats;
    cudaGetSymbolAddress((void**)&xT_hi,   g_xT_hi);
    cudaGetSymbolAddress((void**)&xT_lo,   g_xT_lo);
    cudaGetSymbolAddress((void**)&wr_hi,   g_wr_hi);
    cudaGetSymbolAddress((void**)&wr_lo,   g_wr_lo);
    cudaGetSymbolAddress((void**)&wqkv_hi, g_wqkv_hi);
    cudaGetSymbolAddress((void**)&wqkv_lo, g_wqkv_lo);
    cudaGetSymbolAddress((void**)&wc_hi,   g_wc_hi);
    cudaGetSymbolAddress((void**)&wc_lo,   g_wc_lo);
    cudaGetSymbolAddress((void**)&xrT_hi,  g_xrT_hi);
    cudaGetSymbolAddress((void**)&xrT_lo,  g_xrT_lo);
    cudaGetSymbolAddress((void**)&qkv,     g_qkv);
    cudaGetSymbolAddress((void**)&att,     g_att);
    cudaGetSymbolAddress((void**)&virt,    g_virt);
    cudaGetSymbolAddress((void**)&vT_hi,   g_vT_hi);
    cudaGetSymbolAddress((void**)&vT_lo,   g_vT_lo);
    cudaGetSymbolAddress((void**)&co,      g_co);
    cudaGetSymbolAddress((void**)&stats,   g_stats);

    // weight conversions
    conv_split<<<(512 * 2304 + 255) / 256, 256>>>(w_reduce, wr_hi, wr_lo, 512 * 2304);
    conv_wqkv<<<(3 * 512 * 4608 + 255) / 256, 256>>>(w_q, w_k, w_v, wqkv_hi, wqkv_lo);
    conv_wc<<<(512 * 4608 + 255) / 256, 256>>>(w_conv, wc_hi, wc_lo);

    // x transpose-convert, then 1x1 reduce -> xrT hi/lo directly
    tconv<<<dim3(7, 72, 64), dim3(32, 8)>>>(x, xT_hi, xT_lo, CIN);
    gemm_mma<0, 0><<<dim3(4, 49), 256, GEMM_SMEM>>>(wr_hi, wr_lo, xT_hi, xT_lo,
                                                    nullptr, xrT_hi, xrT_lo);

    // fused qkv conv GEMM -> qT,kT,vT fp32 [n][512]
    gemm_mma<1, 1><<<dim3(12, 49), 256, GEMM_SMEM>>>(wqkv_hi, wqkv_lo, xrT_hi, xrT_lo,
                                                     qkv, nullptr, nullptr);

    const float* q = qkv;
    const float* k = qkv + (long)QO;
    const float* v = qkv + 2 * (long)QO;

    attn_scores<<<HWP, 256>>>(q, k, att);
    softmax_j<<<(HWP * BATCH * 32 + 255) / 256, 256>>>(att);
    attn_apply<<<HWP, 256>>>(att, v, virt);

    gn_stats<<<BATCH, 256>>>(virt, stats);
    gn_split<<<(int)(((long)BATCH * CHW + 255) / 256), 256>>>(virt, stats, gamma, beta,
                                                              vT_hi, vT_lo);

    // final conv GEMM -> coT fp32 [n][512]
    gemm_mma<1, 1><<<dim3(4, 49), 256, GEMM_SMEM>>>(wc_hi, wc_lo, vT_hi, vT_lo,
                                                    co, nullptr, nullptr);

    pool_pred<<<BATCH, 256>>>(xrT_hi, xrT_lo, co, w_pred, out);
}

// round 6
// speedup vs baseline: 1.0072x; 1.0072x over previous
#include <cuda_runtime.h>
#include <cuda_bf16.h>
#include <cstdint>

// ---------------- problem constants ----------------
#define BATCH 64
#define DCH   512
#define CIN   2304
#define HWP   196
#define NTOT  (BATCH * HWP)        // 12544
#define CHW   (DCH * HWP)          // 100352
#define QO    (BATCH * CHW)        // elems per q/k/v tensor

// ---------------- scratch (static device memory) ----------------
__device__ float4 g_xT_hi [(64*196*2304)/8];
__device__ float4 g_xT_lo [(64*196*2304)/8];
__device__ float4 g_wr_hi [(512*2304)/8];
__device__ float4 g_wr_lo [(512*2304)/8];
__device__ float4 g_wqkv_hi[(3*512*4608)/8];
__device__ float4 g_wqkv_lo[(3*512*4608)/8];
__device__ float4 g_wc_hi [(512*4608)/8];
__device__ float4 g_wc_lo [(512*4608)/8];
__device__ float4 g_xrT_hi[(BATCH*CHW)/8];
__device__ float4 g_xrT_lo[(BATCH*CHW)/8];
__device__ float4 g_qkv   [(3*BATCH*CHW)/4];     // qT,kT,vT fp32 [n][512]
__device__ float4 g_att   [(HWP*BATCH*BATCH)/4]; // [p][i][j]
__device__ float4 g_virt  [(BATCH*CHW)/4];       // virtT fp32 [n][512]
__device__ float4 g_vT_hi [(BATCH*CHW)/8];
__device__ float4 g_vT_lo [(BATCH*CHW)/8];
__device__ float4 g_co    [(BATCH*CHW)/4];       // coT fp32 [n][512]
__device__ float  g_stats [2*BATCH];

// ---------------- helpers ----------------
__device__ __forceinline__ uint32_t smem_to_u32(const void* p) {
    uint32_t a;
    asm("{ .reg .u64 t; cvta.to.shared.u64 t, %1; cvt.u32.u64 %0, t; }" : "=r"(a) : "l"(p));
    return a;
}
#define CP_ASYNC16(dst, src, sz) \
    asm volatile("cp.async.cg.shared.global [%0], [%1], 16, %2;" \
                 :: "r"(dst), "l"(src), "r"(sz) : "memory")
#define CP_COMMIT() asm volatile("cp.async.commit_group;" ::: "memory")
#define CP_WAIT1()  asm volatile("cp.async.wait_group 1;" ::: "memory")
#define CP_WAIT0()  asm volatile("cp.async.wait_group 0;" ::: "memory")

#define LDMATRIX_X4(r0, r1, r2, r3, addr) \
    asm volatile("ldmatrix.sync.aligned.m8n8.x4.shared.b16 {%0,%1,%2,%3}, [%4];" \
                 : "=r"(r0), "=r"(r1), "=r"(r2), "=r"(r3) : "r"(addr))

#define MMA16816(d, a0, a1, a2, a3, b0, b1) \
    asm volatile("mma.sync.aligned.m16n8k16.row.col.f32.bf16.bf16.f32 " \
                 "{%0,%1,%2,%3}, {%4,%5,%6,%7}, {%8,%9}, {%0,%1,%2,%3};" \
                 : "+f"((d)[0]), "+f"((d)[1]), "+f"((d)[2]), "+f"((d)[3]) \
                 : "r"(a0), "r"(a1), "r"(a2), "r"(a3), "r"(b0), "r"(b1))

// smem tile rows of 32 bf16 (64B); 16B slots XOR-swizzled by (row>>1)&3
__device__ __forceinline__ uint32_t swz(int row, int slot) {
    return (uint32_t)row * 64u + (uint32_t)((slot ^ ((row >> 1) & 3)) << 4);
}

// ---------------- split-bf16 GEMM via mma.sync (R4 mainloop) ----------------
// D = A*B fp32 via 3 bf16 passes: hi*hi + lo*hi + hi*lo (pass picks operand ptrs).
// MODE 0: KTOT=2304, CB=2304 (1x1 reduce). MODE 1: KTOT=4608 (k=tap*512+c), CB=512.
// OUTM 0: bf16 hi/lo transposed [n][c] out. OUTM 1: fp32 transposed [n][512],
//         tensor s = m0>>9 (fused qkv).
#define STAGE_BYTES 24576          // A 8KB + B 16KB
#define GEMM_SMEM   (3 * STAGE_BYTES)

template<int MODE, int OUTM>
__global__ __launch_bounds__(256)
void gemm_mma(const __nv_bfloat16* __restrict__ Ahi, const __nv_bfloat16* __restrict__ Alo,
              const __nv_bfloat16* __restrict__ Bhi, const __nv_bfloat16* __restrict__ Blo,
              float* __restrict__ Of,
              __nv_bfloat16* __restrict__ Ohi, __nv_bfloat16* __restrict__ Olo)
{
    constexpr int KTOT = MODE ? 4608 : 2304;
    constexpr int CB   = MODE ? 512  : 2304;
    constexpr int CPS  = MODE ? 144  : 72;      // 32-wide K chunks per split pass
    constexpr int TOTAL = 3 * CPS;

    extern __shared__ char smem[];
    const uint32_t sb = smem_to_u32(smem);

    const int t    = threadIdx.x;
    const int lane = t & 31;
    const int wid  = t >> 5;
    const int m0   = blockIdx.x * 128;
    const int n0   = blockIdx.y * 256;

    // ---- load assignments ----
    const int slot  = t & 3;
    const int lrow0 = t >> 2;

    int aoff[2];
    uint32_t adst[2];
#pragma unroll
    for (int i = 0; i < 2; i++) {
        const int r = lrow0 + 64 * i;
        aoff[i] = (m0 + r) * KTOT + slot * 8;
        adst[i] = swz(r, slot);
    }
    int bbase[4], bpy[4], bpx[4];
    uint32_t bdst[4];
#pragma unroll
    for (int i = 0; i < 4; i++) {
        const int r = lrow0 + 64 * i;
        const int n = n0 + r;
        const int b = n / HWP;
        const int p = n - b * HWP;
        bbase[i] = n * CB;
        bpy[i] = p / 14;
        bpx[i] = p - bpy[i] * 14;
        bdst[i] = swz(r, slot);
    }

    auto issue = [&](int chunk, int buf) {
        const uint32_t sa  = sb + (uint32_t)buf * STAGE_BYTES;
        const uint32_t sbm = sa + 8192u;
        const int split = chunk / CPS;
        const int rem   = chunk - split * CPS;
        int kbase, doff, dy = 0, dx = 0;
        if (MODE) {
            const int tap = rem >> 4;
            const int c0  = (rem & 15) * 32;
            kbase = tap * 512 + c0;
            dy = tap / 3 - 1;
            dx = tap - (tap / 3) * 3 - 1;
            doff = (dy * 14 + dx) * CB + c0;
        } else {
            kbase = rem * 32;
            doff  = kbase;
        }
        const __nv_bfloat16* Ap = (split == 1) ? Alo : Ahi;
        const __nv_bfloat16* Bp = (split == 2) ? Blo : Bhi;
#pragma unroll
        for (int i = 0; i < 2; i++)
            CP_ASYNC16(sa + adst[i], Ap + aoff[i] + kbase, 16u);
#pragma unroll
        for (int i = 0; i < 4; i++) {
            uint32_t sz = 16u;
            const __nv_bfloat16* src = Bp + bbase[i] + doff + slot * 8;
            if (MODE) {
                const bool ok = ((unsigned)(bpy[i] + dy) < 14u) &&
                                ((unsigned)(bpx[i] + dx) < 14u);
                if (!ok) { sz = 0u; src = Bp; }
            }
            CP_ASYNC16(sbm + bdst[i], src, sz);
        }
        CP_COMMIT();
    };

    // ---- per-warp fragment addresses ----
    const int wm = (wid & 1) * 64;
    const int wn = (wid >> 1) * 64;
    uint32_t addrA[4][2], addrB[4][2];
#pragma unroll
    for (int mi = 0; mi < 4; mi++) {
        const int row = wm + mi * 16 + (lane & 15);
#pragma unroll
        for (int kh = 0; kh < 2; kh++)
            addrA[mi][kh] = swz(row, kh * 2 + (lane >> 4));
    }
#pragma unroll
    for (int nb = 0; nb < 4; nb++) {
        const int row = wn + nb * 16 + (lane & 7) + ((lane & 16) ? 8 : 0);
#pragma unroll
        for (int kh = 0; kh < 2; kh++)
            addrB[nb][kh] = swz(row, kh * 2 + ((lane >> 3) & 1));
    }

    float acc[4][8][4];
#pragma unroll
    for (int mi = 0; mi < 4; mi++)
#pragma unroll
        for (int ni = 0; ni < 8; ni++)
#pragma unroll
            for (int r = 0; r < 4; r++) acc[mi][ni][r] = 0.0f;

    issue(0, 0);
    issue(1, 1);

    for (int it = 0; it < TOTAL; ++it) {
        CP_WAIT1();
        __syncthreads();
        if (it + 2 < TOTAL) issue(it + 2, (it + 2) % 3);
        else CP_COMMIT();

        const uint32_t sa  = sb + (uint32_t)(it % 3) * STAGE_BYTES;
        const uint32_t sbm = sa + 8192u;
#pragma unroll
        for (int kh = 0; kh < 2; kh++) {
            uint32_t a[4][4], bf[8][2];
#pragma unroll
            for (int mi = 0; mi < 4; mi++)
                LDMATRIX_X4(a[mi][0], a[mi][1], a[mi][2], a[mi][3], sa + addrA[mi][kh]);
#pragma unroll
            for (int nb = 0; nb < 4; nb++) {
                uint32_t r0, r1, r2, r3;
                LDMATRIX_X4(r0, r1, r2, r3, sbm + addrB[nb][kh]);
                bf[2 * nb][0] = r0; bf[2 * nb][1] = r1;
                bf[2 * nb + 1][0] = r2; bf[2 * nb + 1][1] = r3;
            }
#pragma unroll
            for (int mi = 0; mi < 4; mi++)
#pragma unroll
                for (int ni = 0; ni < 8; ni++)
                    MMA16816(acc[mi][ni], a[mi][0], a[mi][1], a[mi][2], a[mi][3],
                             bf[ni][0], bf[ni][1]);
        }
    }

    CP_WAIT0();
    __syncthreads();

    // ---- transposed epilogue: slabs of 32 n via smem, coalesced [n][c] writes ----
    float* smf = (float*)smem;                  // [32][132]
    const int s_tensor = m0 >> 9;
    const int cbase = m0 & 511;
    for (int slab = 0; slab < 8; ++slab) {
        __syncthreads();
        if ((slab >> 1) == (wn >> 6)) {
            const int nsub = (slab & 1) * 32;
#pragma unroll
            for (int ni4 = 0; ni4 < 4; ni4++) {
                const int ni = (nsub >> 3) + ni4;
                const int nl = ni * 8 + (lane & 3) * 2 - nsub;
                const int r0 = wm + (lane >> 2);
#pragma unroll
                for (int mi = 0; mi < 4; mi++) {
                    const int m = r0 + mi * 16;
                    smf[nl * 132 + m]           = acc[mi][ni][0];
                    smf[(nl + 1) * 132 + m]     = acc[mi][ni][1];
                    smf[nl * 132 + m + 8]       = acc[mi][ni][2];
                    smf[(nl + 1) * 132 + m + 8] = acc[mi][ni][3];
                }
            }
        }
        __syncthreads();
        const int nloc = t >> 3;
        const int c16  = (t & 7) * 16;
        const long ng  = n0 + slab * 32 + nloc;
        float vals[16];
#pragma unroll
        for (int j = 0; j < 16; j++) vals[j] = smf[nloc * 132 + c16 + j];
        if (OUTM == 0) {
            uint32_t hw[8], lw[8];
#pragma unroll
            for (int j = 0; j < 8; j++) {
                float v0 = vals[2 * j], v1 = vals[2 * j + 1];
                __nv_bfloat162 hp = __float22bfloat162_rn(make_float2(v0, v1));
                float r0 = v0 - __bfloat162float(__low2bfloat16(hp));
                float r1 = v1 - __bfloat162float(__high2bfloat16(hp));
                __nv_bfloat162 lp = __float22bfloat162_rn(make_float2(r0, r1));
                hw[j] = *(uint32_t*)&hp;
                lw[j] = *(uint32_t*)&lp;
            }
            uint4* ph = (uint4*)(Ohi + ng * 512 + cbase + c16);
            uint4* pl = (uint4*)(Olo + ng * 512 + cbase + c16);
            ph[0] = make_uint4(hw[0], hw[1], hw[2], hw[3]);
            ph[1] = make_uint4(hw[4], hw[5], hw[6], hw[7]);
            pl[0] = make_uint4(lw[0], lw[1], lw[2], lw[3]);
            pl[1] = make_uint4(lw[4], lw[5], lw[6], lw[7]);
        } else {
            float4* po = (float4*)(Of + (long)s_tensor * QO + ng * 512 + cbase + c16);
#pragma unroll
            for (int j = 0; j < 4; j++)
                po[j] = make_float4(vals[4 * j], vals[4 * j + 1], vals[4 * j + 2], vals[4 * j + 3]);
        }
    }
}

// ---------------- conversion kernels ----------------
__global__ __launch_bounds__(256)
void conv_split(const float* __restrict__ in, __nv_bfloat16* __restrict__ hi,
                __nv_bfloat16* __restrict__ lo, int n)
{
    const int i = blockIdx.x * 256 + threadIdx.x;
    if (i >= n) return;
    const float v = in[i];
    const __nv_bfloat16 h = __float2bfloat16(v);
    hi[i] = h;
    lo[i] = __float2bfloat16(v - __bfloat162float(h));
}

__global__ __launch_bounds__(256)
void conv_wqkv(const float* __restrict__ wq, const float* __restrict__ wk,
               const float* __restrict__ wv,
               __nv_bfloat16* __restrict__ hi, __nv_bfloat16* __restrict__ lo)
{
    const int i = blockIdx.x * 256 + threadIdx.x;
    if (i >= 3 * 512 * 4608) return;
    const int s = i / (512 * 4608);
    const int r = i - s * (512 * 4608);
    const int m = r / 4608;
    const int k = r - m * 4608;
    const int kk = k >> 9;
    const int c = k & 511;
    const float* w = (s == 0) ? wq : ((s == 1) ? wk : wv);
    const float v = w[(m * 512 + c) * 9 + kk];
    const __nv_bfloat16 h = __float2bfloat16(v);
    hi[i] = h;
    lo[i] = __float2bfloat16(v - __bfloat162float(h));
}

__global__ __launch_bounds__(256)
void conv_wc(const float* __restrict__ w,
             __nv_bfloat16* __restrict__ hi, __nv_bfloat16* __restrict__ lo)
{
    const int i = blockIdx.x * 256 + threadIdx.x;
    if (i >= 512 * 4608) return;
    const int m = i / 4608;
    const int k = i - m * 4608;
    const int kk = k >> 9;
    const int c = k & 511;
    const float v = w[(m * 512 + c) * 9 + kk];
    const __nv_bfloat16 h = __float2bfloat16(v);
    hi[i] = h;
    lo[i] = __float2bfloat16(v - __bfloat162float(h));
}

// x [b][2304][196] fp32 -> xT [b*196+p][2304] bf16 hi/lo
__global__ __launch_bounds__(256)
void tconv(const float* __restrict__ in, __nv_bfloat16* __restrict__ hi,
           __nv_bfloat16* __restrict__ lo, int C)
{
    __shared__ float tile[32][33];
    const int b = blockIdx.z;
    const int c0 = blockIdx.y * 32;
    const int p0 = blockIdx.x * 32;
    const int tx = threadIdx.x, ty = threadIdx.y;
    const float* src = in + ((long)b * C + c0) * HWP;
    const int p = p0 + tx;
    for (int i = ty; i < 32; i += 8)
        tile[i][tx] = (p < HWP) ? src[i * HWP + p] : 0.0f;
    __syncthreads();
    for (int i = ty; i < 32; i += 8) {
        const int pp = p0 + i;
        if (pp < HWP) {
            const float v = tile[tx][i];
            const __nv_bfloat16 h = __float2bfloat16(v);
            const long o = ((long)b * HWP + pp) * C + c0 + tx;
            hi[o] = h;
            lo[o] = __float2bfloat16(v - __bfloat162float(h));
        }
    }
}

// ---------------- attention on transposed [n][512] fp32 ----------------
__global__ __launch_bounds__(256)
void attn_scores(const float* __restrict__ Q, const float* __restrict__ Kin, float* __restrict__ A)
{
    const int p = blockIdx.x;
    const int t = threadIdx.x;
    __shared__ float qs[64][33];
    __shared__ float ks[64][33];
    float acc[4][4];
#pragma unroll
    for (int a = 0; a < 4; a++)
#pragma unroll
        for (int b4 = 0; b4 < 4; b4++) acc[a][b4] = 0.0f;
    const int ti = (t & 15) * 4;
    const int tj = (t >> 4) * 4;
    for (int ch = 0; ch < 16; ++ch) {
        const int c0 = ch * 32;
        __syncthreads();
        for (int e = t; e < 64 * 32; e += 256) {
            const int i = e >> 5, c = e & 31;
            qs[i][c] = Q[((long)i * HWP + p) * 512 + c0 + c];
            ks[i][c] = Kin[((long)i * HWP + p) * 512 + c0 + c];
        }
        __syncthreads();
#pragma unroll 8
        for (int c = 0; c < 32; ++c) {
            float qa[4], kb[4];
#pragma unroll
            for (int a = 0; a < 4; a++) qa[a] = qs[ti + a][c];
#pragma unroll
            for (int b4 = 0; b4 < 4; b4++) kb[b4] = ks[tj + b4][c];
#pragma unroll
            for (int a = 0; a < 4; a++)
#pragma unroll
                for (int b4 = 0; b4 < 4; b4++) acc[a][b4] = fmaf(qa[a], kb[b4], acc[a][b4]);
        }
    }
    const float scale = 0.044194173824159216f;
    float* Ab = A + (long)p * 4096;
#pragma unroll
    for (int a = 0; a < 4; a++)
#pragma unroll
        for (int b4 = 0; b4 < 4; b4++)
            Ab[(ti + a) * 64 + tj + b4] = acc[a][b4] * scale;
}

__global__ __launch_bounds__(256)
void softmax_j(float* __restrict__ A)
{
    const int gw   = (blockIdx.x * blockDim.x + threadIdx.x) >> 5;
    const int lane = threadIdx.x & 31;
    if (gw >= HWP * BATCH) return;
    float* row = A + (long)gw * 64;
    float v0 = row[lane];
    float v1 = row[lane + 32];
    float m = fmaxf(v0, v1);
#pragma unroll
    for (int o = 16; o > 0; o >>= 1) m = fmaxf(m, __shfl_xor_sync(0xffffffffu, m, o));
    float e0 = __expf(v0 - m);
    float e1 = __expf(v1 - m);
    float ssum = e0 + e1;
#pragma unroll
    for (int o = 16; o > 0; o >>= 1) ssum += __shfl_xor_sync(0xffffffffu, ssum, o);
    const float inv = 1.0f / ssum;
    row[lane]      = e0 * inv;
    row[lane + 32] = e1 * inv;
}

__global__ __launch_bounds__(256)
void attn_apply(const float* __restrict__ A, const float* __restrict__ V, float* __restrict__ Out)
{
    const int p = blockIdx.x;
    const int t = threadIdx.x;
    __shared__ float as[64][65];
    __shared__ float vs[64][33];
    const float* Ab = A + (long)p * 4096;
    for (int e = t; e < 64 * 64; e += 256) {
        const int i = e >> 6, j = e & 63;
        as[i][j] = Ab[i * 64 + j];
    }
    __syncthreads();
    const int ti = (t & 15) * 4;
    const int tc = (t >> 4) * 2;
    for (int ch = 0; ch < 16; ++ch) {
        const int c0 = ch * 32;
        if (ch) __syncthreads();
        for (int e = t; e < 64 * 32; e += 256) {
            const int j = e >> 5, c = e & 31;
            vs[j][c] = V[((long)j * HWP + p) * 512 + c0 + c];
        }
        __syncthreads();
        float acc[4][2];
#pragma unroll
        for (int a = 0; a < 4; a++) { acc[a][0] = 0.0f; acc[a][1] = 0.0f; }
#pragma unroll 8
        for (int j = 0; j < 64; ++j) {
            float vv0 = vs[j][tc];
            float vv1 = vs[j][tc + 1];
#pragma unroll
            for (int a = 0; a < 4; a++) {
                const float av = as[ti + a][j];
                acc[a][0] = fmaf(av, vv0, acc[a][0]);
                acc[a][1] = fmaf(av, vv1, acc[a][1]);
            }
        }
#pragma unroll
        for (int a = 0; a < 4; a++)
            *(float2*)(Out + ((long)(ti + a) * HWP + p) * 512 + c0 + tc) =
                make_float2(acc[a][0], acc[a][1]);
    }
}

// ---------------- GroupNorm stats (virtT contiguous per batch) ----------------
__global__ __launch_bounds__(256)
void gn_stats(const float* __restrict__ Vt, float* __restrict__ stats)
{
    const int i = blockIdx.x;
    const int t = threadIdx.x;
    float s = 0.0f, s2 = 0.0f;
    const float* row = Vt + (long)i * CHW;
    for (int e = t; e < CHW; e += 256) {
        const float v = row[e];
        s += v;
        s2 = fmaf(v, v, s2);
    }
    __shared__ float sh1[256];
    __shared__ float sh2[256];
    sh1[t] = s; sh2[t] = s2;
    __syncthreads();
    for (int st = 128; st > 0; st >>= 1) {
        if (t < st) { sh1[t] += sh1[t + st]; sh2[t] += sh2[t + st]; }
        __syncthreads();
    }
    if (t == 0) {
        const float inv_n = 1.0f / (float)CHW;
        const float mean = sh1[0] * inv_n;
        const float var  = sh2[0] * inv_n - mean * mean;
        stats[2 * i]     = mean;
        stats[2 * i + 1] = rsqrtf(var + 1e-5f);
    }
}

// fused: normalize + affine + relu + bf16 split -> vT_hi/lo [n][512]
__global__ __launch_bounds__(256)
void gn_split(const float* __restrict__ Vt, const float* __restrict__ stats,
              const float* __restrict__ gamma, const float* __restrict__ beta,
              __nv_bfloat16* __restrict__ hi, __nv_bfloat16* __restrict__ lo)
{
    const long idx = (long)blockIdx.x * 256 + threadIdx.x;
    if (idx >= (long)BATCH * CHW) return;
    const int i = (int)(idx / CHW);
    const int c = (int)(idx & 511);
    const float mean = stats[2 * i];
    const float rstd = stats[2 * i + 1];
    float v = (Vt[idx] - mean) * rstd * gamma[c] + beta[c];
    v = fmaxf(v, 0.0f);
    const __nv_bfloat16 h = __float2bfloat16(v);
    hi[idx] = h;
    lo[idx] = __float2bfloat16(v - __bfloat162float(h));
}

// residual (xrT hi+lo) + coT, avg pool over p, dot with w_pred
__global__ __launch_bounds__(256)
void pool_pred(const __nv_bfloat16* __restrict__ Xh, const __nv_bfloat16* __restrict__ Xl,
               const float* __restrict__ CO, const float* __restrict__ Wp,
               float* __restrict__ out)
{
    const int b = blockIdx.x;
    const int t = threadIdx.x;
    float acc = 0.0f;
    const long base = (long)b * CHW;
    for (int e = t; e < CHW; e += 256) {
        const int c = e & 511;
        const float xv = __bfloat162float(Xh[base + e]) + __bfloat162float(Xl[base + e]);
        acc = fmaf(Wp[c], xv + CO[base + e], acc);
    }
    __shared__ float sh[256];
    sh[t] = acc;
    __syncthreads();
    for (int st = 128; st > 0; st >>= 1) {
        if (t < st) sh[t] += sh[t + st];
        __syncthreads();
    }
    if (t == 0) out[b] = sh[0] * (1.0f / (float)HWP);
}

// ---------------- launcher ----------------
extern "C" void kernel_launch(void* const* d_in, const int* in_sizes, int n_in,
                              void* d_out, int out_size)
{
    const float* x        = (const float*)d_in[0];
    const float* w_reduce = (const float*)d_in[1];
    const float* w_q      = (const float*)d_in[2];
    const float* w_k      = (const float*)d_in[3];
    const float* w_v      = (const float*)d_in[4];
    const float* w_conv   = (const float*)d_in[5];
    const float* gamma    = (const float*)d_in[6];
    const float* beta     = (const float*)d_in[7];
    const float* w_pred   = (const float*)d_in[8];
    float* out = (float*)d_out;

    cudaFuncSetAttribute(gemm_mma<0, 0>, cudaFuncAttributeMaxDynamicSharedMemorySize, GEMM_SMEM);
    cudaFuncSetAttribute(gemm_mma<1, 1>, cudaFuncAttributeMaxDynamicSharedMemorySize, GEMM_SMEM);

    __nv_bfloat16 *xT_hi, *xT_lo, *wr_hi, *wr_lo, *wqkv_hi, *wqkv_lo, *wc_hi, *wc_lo;
    __nv_bfloat16 *xrT_hi, *xrT_lo, *vT_hi, *vT_lo;
    float *qkv, *att, *virt, *co, *stats;
    cudaGetSymbolAddress((void**)&xT_hi,   g_xT_hi);
    cudaGetSymbolAddress((void**)&xT_lo,   g_xT_lo);
    cudaGetSymbolAddress((void**)&wr_hi,   g_wr_hi);
    cudaGetSymbolAddress((void**)&wr_lo,   g_wr_lo);
    cudaGetSymbolAddress((void**)&wqkv_hi, g_wqkv_hi);
    cudaGetSymbolAddress((void**)&wqkv_lo, g_wqkv_lo);
    cudaGetSymbolAddress((void**)&wc_hi,   g_wc_hi);
    cudaGetSymbolAddress((void**)&wc_lo,   g_wc_lo);
    cudaGetSymbolAddress((void**)&xrT_hi,  g_xrT_hi);
    cudaGetSymbolAddress((void**)&xrT_lo,  g_xrT_lo);
    cudaGetSymbolAddress((void**)&qkv,     g_qkv);
    cudaGetSymbolAddress((void**)&att,     g_att);
    cudaGetSymbolAddress((void**)&virt,    g_virt);
    cudaGetSymbolAddress((void**)&vT_hi,   g_vT_hi);
    cudaGetSymbolAddress((void**)&vT_lo,   g_vT_lo);
    cudaGetSymbolAddress((void**)&co,      g_co);
    cudaGetSymbolAddress((void**)&stats,   g_stats);

    // weight conversions
    conv_split<<<(512 * 2304 + 255) / 256, 256>>>(w_reduce, wr_hi, wr_lo, 512 * 2304);
    conv_wqkv<<<(3 * 512 * 4608 + 255) / 256, 256>>>(w_q, w_k, w_v, wqkv_hi, wqkv_lo);
    conv_wc<<<(512 * 4608 + 255) / 256, 256>>>(w_conv, wc_hi, wc_lo);

    // x transpose-convert, then 1x1 reduce -> xrT hi/lo directly
    tconv<<<dim3(7, 72, 64), dim3(32, 8)>>>(x, xT_hi, xT_lo, CIN);
    gemm_mma<0, 0><<<dim3(4, 49), 256, GEMM_SMEM>>>(wr_hi, wr_lo, xT_hi, xT_lo,
                                                    nullptr, xrT_hi, xrT_lo);

    // fused qkv conv GEMM -> qT,kT,vT fp32 [n][512]
    gemm_mma<1, 1><<<dim3(12, 49), 256, GEMM_SMEM>>>(wqkv_hi, wqkv_lo, xrT_hi, xrT_lo,
                                                     qkv, nullptr, nullptr);

    const float* q = qkv;
    const float* k = qkv + (long)QO;
    const float* v = qkv + 2 * (long)QO;

    attn_scores<<<HWP, 256>>>(q, k, att);
    softmax_j<<<(HWP * BATCH * 32 + 255) / 256, 256>>>(att);
    attn_apply<<<HWP, 256>>>(att, v, virt);

    gn_stats<<<BATCH, 256>>>(virt, stats);
    gn_split<<<(int)(((long)BATCH * CHW + 255) / 256), 256>>>(virt, stats, gamma, beta,
                                                              vT_hi, vT_lo);

    // final conv GEMM -> coT fp32 [n][512]
    gemm_mma<1, 1><<<dim3(4, 49), 256, GEMM_SMEM>>>(wc_hi, wc_lo, vT_hi, vT_lo,
                                                    co, nullptr, nullptr);

    pool_pred<<<BATCH, 256>>>(xrT_hi, xrT_lo, co, w_pred, out);
}

// round 8
// speedup vs baseline: 5.1824x; 5.1456x over previous
#include <cuda_runtime.h>
#include <cuda_bf16.h>
#include <cstdint>

// ---------------- problem constants ----------------
#define BATCH 64
#define DCH   512
#define CIN   2304
#define HWP   196
#define NTOT  (BATCH * HWP)        // 12544
#define CHW   (DCH * HWP)          // 100352
#define QO    (BATCH * CHW)        // elems per q/k/v tensor

// ---------------- scratch (static device memory) ----------------
__device__ float4 g_xT_hi [(64*196*2304)/8];
__device__ float4 g_xT_lo [(64*196*2304)/8];
__device__ float4 g_wr_hi [(512*2304)/8];
__device__ float4 g_wr_lo [(512*2304)/8];
__device__ float4 g_wqkv_hi[(3*512*4608)/8];
__device__ float4 g_wqkv_lo[(3*512*4608)/8];
__device__ float4 g_wc_hi [(512*4608)/8];
__device__ float4 g_wc_lo [(512*4608)/8];
__device__ float4 g_xrT_hi[(BATCH*CHW)/8];
__device__ float4 g_xrT_lo[(BATCH*CHW)/8];
__device__ float4 g_qkv   [(3*BATCH*CHW)/4];     // qT,kT,vT fp32 [n][512]
__device__ float4 g_att   [(HWP*BATCH*BATCH)/4]; // [p][i][j]
__device__ float4 g_virt  [(BATCH*CHW)/4];       // virtT fp32 [n][512]
__device__ float4 g_vT_hi [(BATCH*CHW)/8];
__device__ float4 g_vT_lo [(BATCH*CHW)/8];
__device__ float4 g_co    [(BATCH*CHW)/4];       // coT fp32 [n][512]
__device__ float  g_stats [2*BATCH];

// ---------------- helpers ----------------
__device__ __forceinline__ uint32_t smem_to_u32(const void* p) {
    uint32_t a;
    asm("{ .reg .u64 t; cvta.to.shared.u64 t, %1; cvt.u32.u64 %0, t; }" : "=r"(a) : "l"(p));
    return a;
}
#define CP_ASYNC16(dst, src, sz) \
    asm volatile("cp.async.cg.shared.global [%0], [%1], 16, %2;" \
                 :: "r"(dst), "l"(src), "r"(sz) : "memory")
#define CP_COMMIT() asm volatile("cp.async.commit_group;" ::: "memory")
#define CP_WAIT1()  asm volatile("cp.async.wait_group 1;" ::: "memory")
#define CP_WAIT0()  asm volatile("cp.async.wait_group 0;" ::: "memory")

#define LDMATRIX_X4(r0, r1, r2, r3, addr) \
    asm volatile("ldmatrix.sync.aligned.m8n8.x4.shared.b16 {%0,%1,%2,%3}, [%4];" \
                 : "=r"(r0), "=r"(r1), "=r"(r2), "=r"(r3) : "r"(addr))

#define MMA16816(d, a0, a1, a2, a3, b0, b1) \
    asm volatile("mma.sync.aligned.m16n8k16.row.col.f32.bf16.bf16.f32 " \
                 "{%0,%1,%2,%3}, {%4,%5,%6,%7}, {%8,%9}, {%0,%1,%2,%3};" \
                 : "+f"((d)[0]), "+f"((d)[1]), "+f"((d)[2]), "+f"((d)[3]) \
                 : "r"(a0), "r"(a1), "r"(a2), "r"(a3), "r"(b0), "r"(b1))

// smem tile rows of 32 bf16 (64B); 16B slots XOR-swizzled by (row>>1)&3
__device__ __forceinline__ uint32_t swz(int row, int slot) {
    return (uint32_t)row * 64u + (uint32_t)((slot ^ ((row >> 1) & 3)) << 4);
}

// ---------------- split-bf16 GEMM via mma.sync (R4 mainloop) ----------------
// D = A*B fp32 via 3 bf16 passes: hi*hi + lo*hi + hi*lo (pass picks operand ptrs).
// MODE 0: KTOT=2304, CB=2304 (1x1 reduce). MODE 1: KTOT=4608 (k=tap*512+c), CB=512.
// OUTM 0: bf16 hi/lo transposed [n][c] out. OUTM 1: fp32 transposed [n][512],
//         tensor s = m0>>9 (fused qkv).
#define STAGE_BYTES 24576          // A 8KB + B 16KB
#define GEMM_SMEM   (3 * STAGE_BYTES)

template<int MODE, int OUTM>
__global__ __launch_bounds__(256)
void gemm_mma(const __nv_bfloat16* __restrict__ Ahi, const __nv_bfloat16* __restrict__ Alo,
              const __nv_bfloat16* __restrict__ Bhi, const __nv_bfloat16* __restrict__ Blo,
              float* __restrict__ Of,
              __nv_bfloat16* __restrict__ Ohi, __nv_bfloat16* __restrict__ Olo)
{
    constexpr int KTOT = MODE ? 4608 : 2304;
    constexpr int CB   = MODE ? 512  : 2304;
    constexpr int CPS  = MODE ? 144  : 72;      // 32-wide K chunks per split pass
    constexpr int TOTAL = 3 * CPS;

    extern __shared__ char smem[];
    const uint32_t sb = smem_to_u32(smem);

    const int t    = threadIdx.x;
    const int lane = t & 31;
    const int wid  = t >> 5;
    const int m0   = blockIdx.x * 128;
    const int n0   = blockIdx.y * 256;

    // ---- load assignments ----
    const int slot  = t & 3;
    const int lrow0 = t >> 2;

    int aoff[2];
    uint32_t adst[2];
#pragma unroll
    for (int i = 0; i < 2; i++) {
        const int r = lrow0 + 64 * i;
        aoff[i] = (m0 + r) * KTOT + slot * 8;
        adst[i] = swz(r, slot);
    }
    int bbase[4], bpy[4], bpx[4];
    uint32_t bdst[4];
#pragma unroll
    for (int i = 0; i < 4; i++) {
        const int r = lrow0 + 64 * i;
        const int n = n0 + r;
        const int b = n / HWP;
        const int p = n - b * HWP;
        bbase[i] = n * CB;
        bpy[i] = p / 14;
        bpx[i] = p - bpy[i] * 14;
        bdst[i] = swz(r, slot);
    }

    auto issue = [&](int chunk, int buf) {
        const uint32_t sa  = sb + (uint32_t)buf * STAGE_BYTES;
        const uint32_t sbm = sa + 8192u;
        const int split = chunk / CPS;
        const int rem   = chunk - split * CPS;
        int kbase, doff, dy = 0, dx = 0;
        if (MODE) {
            const int tap = rem >> 4;
            const int c0  = (rem & 15) * 32;
            kbase = tap * 512 + c0;
            dy = tap / 3 - 1;
            dx = tap - (tap / 3) * 3 - 1;
            doff = (dy * 14 + dx) * CB + c0;
        } else {
            kbase = rem * 32;
            doff  = kbase;
        }
        const __nv_bfloat16* Ap = (split == 1) ? Alo : Ahi;
        const __nv_bfloat16* Bp = (split == 2) ? Blo : Bhi;
#pragma unroll
        for (int i = 0; i < 2; i++)
            CP_ASYNC16(sa + adst[i], Ap + aoff[i] + kbase, 16u);
#pragma unroll
        for (int i = 0; i < 4; i++) {
            uint32_t sz = 16u;
            const __nv_bfloat16* src = Bp + bbase[i] + doff + slot * 8;
            if (MODE) {
                const bool ok = ((unsigned)(bpy[i] + dy) < 14u) &&
                                ((unsigned)(bpx[i] + dx) < 14u);
                if (!ok) { sz = 0u; src = Bp; }
            }
            CP_ASYNC16(sbm + bdst[i], src, sz);
        }
        CP_COMMIT();
    };

    // ---- per-warp fragment addresses ----
    const int wm = (wid & 1) * 64;
    const int wn = (wid >> 1) * 64;
    uint32_t addrA[4][2], addrB[4][2];
#pragma unroll
    for (int mi = 0; mi < 4; mi++) {
        const int row = wm + mi * 16 + (lane & 15);
#pragma unroll
        for (int kh = 0; kh < 2; kh++)
            addrA[mi][kh] = swz(row, kh * 2 + (lane >> 4));
    }
#pragma unroll
    for (int nb = 0; nb < 4; nb++) {
        const int row = wn + nb * 16 + (lane & 7) + ((lane & 16) ? 8 : 0);
#pragma unroll
        for (int kh = 0; kh < 2; kh++)
            addrB[nb][kh] = swz(row, kh * 2 + ((lane >> 3) & 1));
    }

    float acc[4][8][4];
#pragma unroll
    for (int mi = 0; mi < 4; mi++)
#pragma unroll
        for (int ni = 0; ni < 8; ni++)
#pragma unroll
            for (int r = 0; r < 4; r++) acc[mi][ni][r] = 0.0f;

    issue(0, 0);
    issue(1, 1);

    for (int it = 0; it < TOTAL; ++it) {
        CP_WAIT1();
        __syncthreads();
        if (it + 2 < TOTAL) issue(it + 2, (it + 2) % 3);
        else CP_COMMIT();

        const uint32_t sa  = sb + (uint32_t)(it % 3) * STAGE_BYTES;
        const uint32_t sbm = sa + 8192u;
#pragma unroll
        for (int kh = 0; kh < 2; kh++) {
            uint32_t a[4][4], bf[8][2];
#pragma unroll
            for (int mi = 0; mi < 4; mi++)
                LDMATRIX_X4(a[mi][0], a[mi][1], a[mi][2], a[mi][3], sa + addrA[mi][kh]);
#pragma unroll
            for (int nb = 0; nb < 4; nb++) {
                uint32_t r0, r1, r2, r3;
                LDMATRIX_X4(r0, r1, r2, r3, sbm + addrB[nb][kh]);
                bf[2 * nb][0] = r0; bf[2 * nb][1] = r1;
                bf[2 * nb + 1][0] = r2; bf[2 * nb + 1][1] = r3;
            }
#pragma unroll
            for (int mi = 0; mi < 4; mi++)
#pragma unroll
                for (int ni = 0; ni < 8; ni++)
                    MMA16816(acc[mi][ni], a[mi][0], a[mi][1], a[mi][2], a[mi][3],
                             bf[ni][0], bf[ni][1]);
        }
    }

    CP_WAIT0();
    __syncthreads();

    // ---- transposed epilogue: slabs of 32 n via smem, coalesced [n][c] writes ----
    // NOTE: slab loop MUST be fully unrolled so acc[][] indexing stays
    // compile-time constant — dynamic indexing demotes acc to local memory
    // and poisons the mainloop (R5/R6 regression root cause).
    float* smf = (float*)smem;                  // [32][132]
    const int s_tensor = m0 >> 9;
    const int cbase = m0 & 511;
#pragma unroll
    for (int slab = 0; slab < 8; ++slab) {
        __syncthreads();
        if ((slab >> 1) == (wn >> 6)) {
            const int nsub = (slab & 1) * 32;
#pragma unroll
            for (int ni4 = 0; ni4 < 4; ni4++) {
                const int ni = (nsub >> 3) + ni4;
                const int nl = ni * 8 + (lane & 3) * 2 - nsub;
                const int r0 = wm + (lane >> 2);
#pragma unroll
                for (int mi = 0; mi < 4; mi++) {
                    const int m = r0 + mi * 16;
                    smf[nl * 132 + m]           = acc[mi][ni][0];
                    smf[(nl + 1) * 132 + m]     = acc[mi][ni][1];
                    smf[nl * 132 + m + 8]       = acc[mi][ni][2];
                    smf[(nl + 1) * 132 + m + 8] = acc[mi][ni][3];
                }
            }
        }
        __syncthreads();
        const int nloc = t >> 3;
        const int c16  = (t & 7) * 16;
        const long ng  = n0 + slab * 32 + nloc;
        float vals[16];
#pragma unroll
        for (int j = 0; j < 16; j++) vals[j] = smf[nloc * 132 + c16 + j];
        if (OUTM == 0) {
            uint32_t hw[8], lw[8];
#pragma unroll
            for (int j = 0; j < 8; j++) {
                float v0 = vals[2 * j], v1 = vals[2 * j + 1];
                __nv_bfloat162 hp = __float22bfloat162_rn(make_float2(v0, v1));
                float r0 = v0 - __bfloat162float(__low2bfloat16(hp));
                float r1 = v1 - __bfloat162float(__high2bfloat16(hp));
                __nv_bfloat162 lp = __float22bfloat162_rn(make_float2(r0, r1));
                hw[j] = *(uint32_t*)&hp;
                lw[j] = *(uint32_t*)&lp;
            }
            uint4* ph = (uint4*)(Ohi + ng * 512 + cbase + c16);
            uint4* pl = (uint4*)(Olo + ng * 512 + cbase + c16);
            ph[0] = make_uint4(hw[0], hw[1], hw[2], hw[3]);
            ph[1] = make_uint4(hw[4], hw[5], hw[6], hw[7]);
            pl[0] = make_uint4(lw[0], lw[1], lw[2], lw[3]);
            pl[1] = make_uint4(lw[4], lw[5], lw[6], lw[7]);
        } else {
            float4* po = (float4*)(Of + (long)s_tensor * QO + ng * 512 + cbase + c16);
#pragma unroll
            for (int j = 0; j < 4; j++)
                po[j] = make_float4(vals[4 * j], vals[4 * j + 1], vals[4 * j + 2], vals[4 * j + 3]);
        }
    }
}

// ---------------- conversion kernels ----------------
__global__ __launch_bounds__(256)
void conv_split(const float* __restrict__ in, __nv_bfloat16* __restrict__ hi,
                __nv_bfloat16* __restrict__ lo, int n)
{
    const int i = blockIdx.x * 256 + threadIdx.x;
    if (i >= n) return;
    const float v = in[i];
    const __nv_bfloat16 h = __float2bfloat16(v);
    hi[i] = h;
    lo[i] = __float2bfloat16(v - __bfloat162float(h));
}

__global__ __launch_bounds__(256)
void conv_wqkv(const float* __restrict__ wq, const float* __restrict__ wk,
               const float* __restrict__ wv,
               __nv_bfloat16* __restrict__ hi, __nv_bfloat16* __restrict__ lo)
{
    const int i = blockIdx.x * 256 + threadIdx.x;
    if (i >= 3 * 512 * 4608) return;
    const int s = i / (512 * 4608);
    const int r = i - s * (512 * 4608);
    const int m = r / 4608;
    const int k = r - m * 4608;
    const int kk = k >> 9;
    const int c = k & 511;
    const float* w = (s == 0) ? wq : ((s == 1) ? wk : wv);
    const float v = w[(m * 512 + c) * 9 + kk];
    const __nv_bfloat16 h = __float2bfloat16(v);
    hi[i] = h;
    lo[i] = __float2bfloat16(v - __bfloat162float(h));
}

__global__ __launch_bounds__(256)
void conv_wc(const float* __restrict__ w,
             __nv_bfloat16* __restrict__ hi, __nv_bfloat16* __restrict__ lo)
{
    const int i = blockIdx.x * 256 + threadIdx.x;
    if (i >= 512 * 4608) return;
    const int m = i / 4608;
    const int k = i - m * 4608;
    const int kk = k >> 9;
    const int c = k & 511;
    const float v = w[(m * 512 + c) * 9 + kk];
    const __nv_bfloat16 h = __float2bfloat16(v);
    hi[i] = h;
    lo[i] = __float2bfloat16(v - __bfloat162float(h));
}

// x [b][2304][196] fp32 -> xT [b*196+p][2304] bf16 hi/lo
__global__ __launch_bounds__(256)
void tconv(const float* __restrict__ in, __nv_bfloat16* __restrict__ hi,
           __nv_bfloat16* __restrict__ lo, int C)
{
    __shared__ float tile[32][33];
    const int b = blockIdx.z;
    const int c0 = blockIdx.y * 32;
    const int p0 = blockIdx.x * 32;
    const int tx = threadIdx.x, ty = threadIdx.y;
    const float* src = in + ((long)b * C + c0) * HWP;
    const int p = p0 + tx;
    for (int i = ty; i < 32; i += 8)
        tile[i][tx] = (p < HWP) ? src[i * HWP + p] : 0.0f;
    __syncthreads();
    for (int i = ty; i < 32; i += 8) {
        const int pp = p0 + i;
        if (pp < HWP) {
            const float v = tile[tx][i];
            const __nv_bfloat16 h = __float2bfloat16(v);
            const long o = ((long)b * HWP + pp) * C + c0 + tx;
            hi[o] = h;
            lo[o] = __float2bfloat16(v - __bfloat162float(h));
        }
    }
}

// ---------------- attention on transposed [n][512] fp32 ----------------
__global__ __launch_bounds__(256)
void attn_scores(const float* __restrict__ Q, const float* __restrict__ Kin, float* __restrict__ A)
{
    const int p = blockIdx.x;
    const int t = threadIdx.x;
    __shared__ float qs[64][33];
    __shared__ float ks[64][33];
    float acc[4][4];
#pragma unroll
    for (int a = 0; a < 4; a++)
#pragma unroll
        for (int b4 = 0; b4 < 4; b4++) acc[a][b4] = 0.0f;
    const int ti = (t & 15) * 4;
    const int tj = (t >> 4) * 4;
    for (int ch = 0; ch < 16; ++ch) {
        const int c0 = ch * 32;
        __syncthreads();
        for (int e = t; e < 64 * 32; e += 256) {
            const int i = e >> 5, c = e & 31;
            qs[i][c] = Q[((long)i * HWP + p) * 512 + c0 + c];
            ks[i][c] = Kin[((long)i * HWP + p) * 512 + c0 + c];
        }
        __syncthreads();
#pragma unroll 8
        for (int c = 0; c < 32; ++c) {
            float qa[4], kb[4];
#pragma unroll
            for (int a = 0; a < 4; a++) qa[a] = qs[ti + a][c];
#pragma unroll
            for (int b4 = 0; b4 < 4; b4++) kb[b4] = ks[tj + b4][c];
#pragma unroll
            for (int a = 0; a < 4; a++)
#pragma unroll
                for (int b4 = 0; b4 < 4; b4++) acc[a][b4] = fmaf(qa[a], kb[b4], acc[a][b4]);
        }
    }
    const float scale = 0.044194173824159216f;
    float* Ab = A + (long)p * 4096;
#pragma unroll
    for (int a = 0; a < 4; a++)
#pragma unroll
        for (int b4 = 0; b4 < 4; b4++)
            Ab[(ti + a) * 64 + tj + b4] = acc[a][b4] * scale;
}

__global__ __launch_bounds__(256)
void softmax_j(float* __restrict__ A)
{
    const int gw   = (blockIdx.x * blockDim.x + threadIdx.x) >> 5;
    const int lane = threadIdx.x & 31;
    if (gw >= HWP * BATCH) return;
    float* row = A + (long)gw * 64;
    float v0 = row[lane];
    float v1 = row[lane + 32];
    float m = fmaxf(v0, v1);
#pragma unroll
    for (int o = 16; o > 0; o >>= 1) m = fmaxf(m, __shfl_xor_sync(0xffffffffu, m, o));
    float e0 = __expf(v0 - m);
    float e1 = __expf(v1 - m);
    float ssum = e0 + e1;
#pragma unroll
    for (int o = 16; o > 0; o >>= 1) ssum += __shfl_xor_sync(0xffffffffu, ssum, o);
    const float inv = 1.0f / ssum;
    row[lane]      = e0 * inv;
    row[lane + 32] = e1 * inv;
}

__global__ __launch_bounds__(256)
void attn_apply(const float* __restrict__ A, const float* __restrict__ V, float* __restrict__ Out)
{
    const int p = blockIdx.x;
    const int t = threadIdx.x;
    __shared__ float as[64][65];
    __shared__ float vs[64][33];
    const float* Ab = A + (long)p * 4096;
    for (int e = t; e < 64 * 64; e += 256) {
        const int i = e >> 6, j = e & 63;
        as[i][j] = Ab[i * 64 + j];
    }
    __syncthreads();
    const int ti = (t & 15) * 4;
    const int tc = (t >> 4) * 2;
    for (int ch = 0; ch < 16; ++ch) {
        const int c0 = ch * 32;
        if (ch) __syncthreads();
        for (int e = t; e < 64 * 32; e += 256) {
            const int j = e >> 5, c = e & 31;
            vs[j][c] = V[((long)j * HWP + p) * 512 + c0 + c];
        }
        __syncthreads();
        float acc[4][2];
#pragma unroll
        for (int a = 0; a < 4; a++) { acc[a][0] = 0.0f; acc[a][1] = 0.0f; }
#pragma unroll 8
        for (int j = 0; j < 64; ++j) {
            float vv0 = vs[j][tc];
            float vv1 = vs[j][tc + 1];
#pragma unroll
            for (int a = 0; a < 4; a++) {
                const float av = as[ti + a][j];
                acc[a][0] = fmaf(av, vv0, acc[a][0]);
                acc[a][1] = fmaf(av, vv1, acc[a][1]);
            }
        }
#pragma unroll
        for (int a = 0; a < 4; a++)
            *(float2*)(Out + ((long)(ti + a) * HWP + p) * 512 + c0 + tc) =
                make_float2(acc[a][0], acc[a][1]);
    }
}

// ---------------- GroupNorm stats (virtT contiguous per batch) ----------------
__global__ __launch_bounds__(256)
void gn_stats(const float* __restrict__ Vt, float* __restrict__ stats)
{
    const int i = blockIdx.x;
    const int t = threadIdx.x;
    float s = 0.0f, s2 = 0.0f;
    const float* row = Vt + (long)i * CHW;
    for (int e = t; e < CHW; e += 256) {
        const float v = row[e];
        s += v;
        s2 = fmaf(v, v, s2);
    }
    __shared__ float sh1[256];
    __shared__ float sh2[256];
    sh1[t] = s; sh2[t] = s2;
    __syncthreads();
    for (int st = 128; st > 0; st >>= 1) {
        if (t < st) { sh1[t] += sh1[t + st]; sh2[t] += sh2[t + st]; }
        __syncthreads();
    }
    if (t == 0) {
        const float inv_n = 1.0f / (float)CHW;
        const float mean = sh1[0] * inv_n;
        const float var  = sh2[0] * inv_n - mean * mean;
        stats[2 * i]     = mean;
        stats[2 * i + 1] = rsqrtf(var + 1e-5f);
    }
}

// fused: normalize + affine + relu + bf16 split -> vT_hi/lo [n][512]
__global__ __launch_bounds__(256)
void gn_split(const float* __restrict__ Vt, const float* __restrict__ stats,
              const float* __restrict__ gamma, const float* __restrict__ beta,
              __nv_bfloat16* __restrict__ hi, __nv_bfloat16* __restrict__ lo)
{
    const long idx = (long)blockIdx.x * 256 + threadIdx.x;
    if (idx >= (long)BATCH * CHW) return;
    const int i = (int)(idx / CHW);
    const int c = (int)(idx & 511);
    const float mean = stats[2 * i];
    const float rstd = stats[2 * i + 1];
    float v = (Vt[idx] - mean) * rstd * gamma[c] + beta[c];
    v = fmaxf(v, 0.0f);
    const __nv_bfloat16 h = __float2bfloat16(v);
    hi[idx] = h;
    lo[idx] = __float2bfloat16(v - __bfloat162float(h));
}

// residual (xrT hi+lo) + coT, avg pool over p, dot with w_pred
__global__ __launch_bounds__(256)
void pool_pred(const __nv_bfloat16* __restrict__ Xh, const __nv_bfloat16* __restrict__ Xl,
               const float* __restrict__ CO, const float* __restrict__ Wp,
               float* __restrict__ out)
{
    const int b = blockIdx.x;
    const int t = threadIdx.x;
    float acc = 0.0f;
    const long base = (long)b * CHW;
    for (int e = t; e < CHW; e += 256) {
        const int c = e & 511;
        const float xv = __bfloat162float(Xh[base + e]) + __bfloat162float(Xl[base + e]);
        acc = fmaf(Wp[c], xv + CO[base + e], acc);
    }
    __shared__ float sh[256];
    sh[t] = acc;
    __syncthreads();
    for (int st = 128; st > 0; st >>= 1) {
        if (t < st) sh[t] += sh[t + st];
        __syncthreads();
    }
    if (t == 0) out[b] = sh[0] * (1.0f / (float)HWP);
}

// ---------------- launcher ----------------
extern "C" void kernel_launch(void* const* d_in, const int* in_sizes, int n_in,
                              void* d_out, int out_size)
{
    const float* x        = (const float*)d_in[0];
    const float* w_reduce = (const float*)d_in[1];
    const float* w_q      = (const float*)d_in[2];
    const float* w_k      = (const float*)d_in[3];
    const float* w_v      = (const float*)d_in[4];
    const float* w_conv   = (const float*)d_in[5];
    const float* gamma    = (const float*)d_in[6];
    const float* beta     = (const float*)d_in[7];
    const float* w_pred   = (const float*)d_in[8];
    float* out = (float*)d_out;

    cudaFuncSetAttribute(gemm_mma<0, 0>, cudaFuncAttributeMaxDynamicSharedMemorySize, GEMM_SMEM);
    cudaFuncSetAttribute(gemm_mma<1, 1>, cudaFuncAttributeMaxDynamicSharedMemorySize, GEMM_SMEM);

    __nv_bfloat16 *xT_hi, *xT_lo, *wr_hi, *wr_lo, *wqkv_hi, *wqkv_lo, *wc_hi, *wc_lo;
    __nv_bfloat16 *xrT_hi, *xrT_lo, *vT_hi, *vT_lo;
    float *qkv, *att, *virt, *co, *stats;
    cudaGetSymbolAddress((void**)&xT_hi,   g_xT_hi);
    cudaGetSymbolAddress((void**)&xT_lo,   g_xT_lo);
    cudaGetSymbolAddress((void**)&wr_hi,   g_wr_hi);
    cudaGetSymbolAddress((void**)&wr_lo,   g_wr_lo);
    cudaGetSymbolAddress((void**)&wqkv_hi, g_wqkv_hi);
    cudaGetSymbolAddress((void**)&wqkv_lo, g_wqkv_lo);
    cudaGetSymbolAddress((void**)&wc_hi,   g_wc_hi);
    cudaGetSymbolAddress((void**)&wc_lo,   g_wc_lo);
    cudaGetSymbolAddress((void**)&xrT_hi,  g_xrT_hi);
    cudaGetSymbolAddress((void**)&xrT_lo,  g_xrT_lo);
    cudaGetSymbolAddress((void**)&qkv,     g_qkv);
    cudaGetSymbolAddress((void**)&att,     g_att);
    cudaGetSymbolAddress((void**)&virt,    g_virt);
    cudaGetSymbolAddress((void**)&vT_hi,   g_vT_hi);
    cudaGetSymbolAddress((void**)&vT_lo,   g_vT_lo);
    cudaGetSymbolAddress((void**)&co,      g_co);
    cudaGetSymbolAddress((void**)&stats,   g_stats);

    // weight conversions
    conv_split<<<(512 * 2304 + 255) / 256, 256>>>(w_reduce, wr_hi, wr_lo, 512 * 2304);
    conv_wqkv<<<(3 * 512 * 4608 + 255) / 256, 256>>>(w_q, w_k, w_v, wqkv_hi, wqkv_lo);
    conv_wc<<<(512 * 4608 + 255) / 256, 256>>>(w_conv, wc_hi, wc_lo);

    // x transpose-convert, then 1x1 reduce -> xrT hi/lo directly
    tconv<<<dim3(7, 72, 64), dim3(32, 8)>>>(x, xT_hi, xT_lo, CIN);
    gemm_mma<0, 0><<<dim3(4, 49), 256, GEMM_SMEM>>>(wr_hi, wr_lo, xT_hi, xT_lo,
                                                    nullptr, xrT_hi, xrT_lo);

    // fused qkv conv GEMM -> qT,kT,vT fp32 [n][512]
    gemm_mma<1, 1><<<dim3(12, 49), 256, GEMM_SMEM>>>(wqkv_hi, wqkv_lo, xrT_hi, xrT_lo,
                                                     qkv, nullptr, nullptr);

    const float* q = qkv;
    const float* k = qkv + (long)QO;
    const float* v = qkv + 2 * (long)QO;

    attn_scores<<<HWP, 256>>>(q, k, att);
    softmax_j<<<(HWP * BATCH * 32 + 255) / 256, 256>>>(att);
    attn_apply<<<HWP, 256>>>(att, v, virt);

    gn_stats<<<BATCH, 256>>>(virt, stats);
    gn_split<<<(int)(((long)BATCH * CHW + 255) / 256), 256>>>(virt, stats, gamma, beta,
                                                              vT_hi, vT_lo);

    // final conv GEMM -> coT fp32 [n][512]
    gemm_mma<1, 1><<<dim3(4, 49), 256, GEMM_SMEM>>>(wc_hi, wc_lo, vT_hi, vT_lo,
                                                    co, nullptr, nullptr);

    pool_pred<<<BATCH, 256>>>(xrT_hi, xrT_lo, co, w_pred, out);
}

// round 9
// speedup vs baseline: 5.1845x; 1.0004x over previous
#include <cuda_runtime.h>
#include <cuda_bf16.h>
#include <cstdint>

// ---------------- problem constants ----------------
#define BATCH 64
#define DCH   512
#define CIN   2304
#define HWP   196
#define NTOT  (BATCH * HWP)        // 12544
#define CHW   (DCH * HWP)          // 100352
#define QO    (BATCH * CHW)        // elems per q/k/v tensor

// ---------------- scratch (static device memory) ----------------
__device__ float4 g_xT_hi [(64*196*2304)/8];
__device__ float4 g_xT_lo [(64*196*2304)/8];
__device__ float4 g_wr_hi [(512*2304)/8];
__device__ float4 g_wr_lo [(512*2304)/8];
__device__ float4 g_wqkv_hi[(3*512*4608)/8];
__device__ float4 g_wqkv_lo[(3*512*4608)/8];
__device__ float4 g_wc_hi [(512*4608)/8];
__device__ float4 g_wc_lo [(512*4608)/8];
__device__ float4 g_xrT_hi[(BATCH*CHW)/8];
__device__ float4 g_xrT_lo[(BATCH*CHW)/8];
__device__ float4 g_qkv   [(3*BATCH*CHW)/4];     // qT,kT,vT fp32 [n][512]
__device__ float4 g_att   [(HWP*BATCH*BATCH)/4]; // [p][i][j]
__device__ float4 g_virt  [(BATCH*CHW)/4];       // virtT fp32 [n][512]
__device__ float4 g_vT_hi [(BATCH*CHW)/8];
__device__ float4 g_vT_lo [(BATCH*CHW)/8];
__device__ float4 g_co    [(BATCH*CHW)/4];       // coT fp32 [n][512]
__device__ float  g_stats [2*BATCH];

// ---------------- helpers ----------------
__device__ __forceinline__ uint32_t smem_to_u32(const void* p) {
    uint32_t a;
    asm("{ .reg .u64 t; cvta.to.shared.u64 t, %1; cvt.u32.u64 %0, t; }" : "=r"(a) : "l"(p));
    return a;
}
#define CP_ASYNC16(dst, src, sz) \
    asm volatile("cp.async.cg.shared.global [%0], [%1], 16, %2;" \
                 :: "r"(dst), "l"(src), "r"(sz) : "memory")
#define CP_COMMIT() asm volatile("cp.async.commit_group;" ::: "memory")
#define CP_WAIT1()  asm volatile("cp.async.wait_group 1;" ::: "memory")
#define CP_WAIT0()  asm volatile("cp.async.wait_group 0;" ::: "memory")

#define LDMATRIX_X4(r0, r1, r2, r3, addr) \
    asm volatile("ldmatrix.sync.aligned.m8n8.x4.shared.b16 {%0,%1,%2,%3}, [%4];" \
                 : "=r"(r0), "=r"(r1), "=r"(r2), "=r"(r3) : "r"(addr))

#define MMA16816(d, a0, a1, a2, a3, b0, b1) \
    asm volatile("mma.sync.aligned.m16n8k16.row.col.f32.bf16.bf16.f32 " \
                 "{%0,%1,%2,%3}, {%4,%5,%6,%7}, {%8,%9}, {%0,%1,%2,%3};" \
                 : "+f"((d)[0]), "+f"((d)[1]), "+f"((d)[2]), "+f"((d)[3]) \
                 : "r"(a0), "r"(a1), "r"(a2), "r"(a3), "r"(b0), "r"(b1))

// smem tile rows of 32 bf16 (64B); 16B slots XOR-swizzled by (row>>1)&3
__device__ __forceinline__ uint32_t swz(int row, int slot) {
    return (uint32_t)row * 64u + (uint32_t)((slot ^ ((row >> 1) & 3)) << 4);
}

// ---------------- split-bf16 GEMM via mma.sync (R4 mainloop) ----------------
// D = A*B fp32 via 3 bf16 passes: hi*hi + lo*hi + hi*lo (pass picks operand ptrs).
// MODE 0: KTOT=2304, CB=2304 (1x1 reduce). MODE 1: KTOT=4608 (k=tap*512+c), CB=512.
// OUTM 0: bf16 hi/lo transposed [n][c] out. OUTM 1: fp32 transposed [n][512],
//         tensor s = m0>>9 (fused qkv).
#define STAGE_BYTES 24576          // A 8KB + B 16KB
#define GEMM_SMEM   (3 * STAGE_BYTES)

template<int MODE, int OUTM>
__global__ __launch_bounds__(256)
void gemm_mma(const __nv_bfloat16* __restrict__ Ahi, const __nv_bfloat16* __restrict__ Alo,
              const __nv_bfloat16* __restrict__ Bhi, const __nv_bfloat16* __restrict__ Blo,
              float* __restrict__ Of,
              __nv_bfloat16* __restrict__ Ohi, __nv_bfloat16* __restrict__ Olo)
{
    constexpr int KTOT = MODE ? 4608 : 2304;
    constexpr int CB   = MODE ? 512  : 2304;
    constexpr int CPS  = MODE ? 144  : 72;      // 32-wide K chunks per split pass
    constexpr int TOTAL = 3 * CPS;

    extern __shared__ char smem[];
    const uint32_t sb = smem_to_u32(smem);

    const int t    = threadIdx.x;
    const int lane = t & 31;
    const int wid  = t >> 5;
    const int m0   = blockIdx.x * 128;
    const int n0   = blockIdx.y * 256;

    // ---- load assignments ----
    const int slot  = t & 3;
    const int lrow0 = t >> 2;

    int aoff[2];
    uint32_t adst[2];
#pragma unroll
    for (int i = 0; i < 2; i++) {
        const int r = lrow0 + 64 * i;
        aoff[i] = (m0 + r) * KTOT + slot * 8;
        adst[i] = swz(r, slot);
    }
    int bbase[4], bpy[4], bpx[4];
    uint32_t bdst[4];
#pragma unroll
    for (int i = 0; i < 4; i++) {
        const int r = lrow0 + 64 * i;
        const int n = n0 + r;
        const int b = n / HWP;
        const int p = n - b * HWP;
        bbase[i] = n * CB;
        bpy[i] = p / 14;
        bpx[i] = p - bpy[i] * 14;
        bdst[i] = swz(r, slot);
    }

    auto issue = [&](int chunk, int buf) {
        const uint32_t sa  = sb + (uint32_t)buf * STAGE_BYTES;
        const uint32_t sbm = sa + 8192u;
        const int split = chunk / CPS;
        const int rem   = chunk - split * CPS;
        int kbase, doff, dy = 0, dx = 0;
        if (MODE) {
            const int tap = rem >> 4;
            const int c0  = (rem & 15) * 32;
            kbase = tap * 512 + c0;
            dy = tap / 3 - 1;
            dx = tap - (tap / 3) * 3 - 1;
            doff = (dy * 14 + dx) * CB + c0;
        } else {
            kbase = rem * 32;
            doff  = kbase;
        }
        const __nv_bfloat16* Ap = (split == 1) ? Alo : Ahi;
        const __nv_bfloat16* Bp = (split == 2) ? Blo : Bhi;
#pragma unroll
        for (int i = 0; i < 2; i++)
            CP_ASYNC16(sa + adst[i], Ap + aoff[i] + kbase, 16u);
#pragma unroll
        for (int i = 0; i < 4; i++) {
            uint32_t sz = 16u;
            const __nv_bfloat16* src = Bp + bbase[i] + doff + slot * 8;
            if (MODE) {
                const bool ok = ((unsigned)(bpy[i] + dy) < 14u) &&
                                ((unsigned)(bpx[i] + dx) < 14u);
                if (!ok) { sz = 0u; src = Bp; }
            }
            CP_ASYNC16(sbm + bdst[i], src, sz);
        }
        CP_COMMIT();
    };

    // ---- per-warp fragment addresses ----
    const int wm = (wid & 1) * 64;
    const int wn = (wid >> 1) * 64;
    uint32_t addrA[4][2], addrB[4][2];
#pragma unroll
    for (int mi = 0; mi < 4; mi++) {
        const int row = wm + mi * 16 + (lane & 15);
#pragma unroll
        for (int kh = 0; kh < 2; kh++)
            addrA[mi][kh] = swz(row, kh * 2 + (lane >> 4));
    }
#pragma unroll
    for (int nb = 0; nb < 4; nb++) {
        const int row = wn + nb * 16 + (lane & 7) + ((lane & 16) ? 8 : 0);
#pragma unroll
        for (int kh = 0; kh < 2; kh++)
            addrB[nb][kh] = swz(row, kh * 2 + ((lane >> 3) & 1));
    }

    float acc[4][8][4];
#pragma unroll
    for (int mi = 0; mi < 4; mi++)
#pragma unroll
        for (int ni = 0; ni < 8; ni++)
#pragma unroll
            for (int r = 0; r < 4; r++) acc[mi][ni][r] = 0.0f;

    issue(0, 0);
    issue(1, 1);

    for (int it = 0; it < TOTAL; ++it) {
        CP_WAIT1();
        __syncthreads();
        if (it + 2 < TOTAL) issue(it + 2, (it + 2) % 3);
        else CP_COMMIT();

        const uint32_t sa  = sb + (uint32_t)(it % 3) * STAGE_BYTES;
        const uint32_t sbm = sa + 8192u;
#pragma unroll
        for (int kh = 0; kh < 2; kh++) {
            uint32_t a[4][4], bf[8][2];
#pragma unroll
            for (int mi = 0; mi < 4; mi++)
                LDMATRIX_X4(a[mi][0], a[mi][1], a[mi][2], a[mi][3], sa + addrA[mi][kh]);
#pragma unroll
            for (int nb = 0; nb < 4; nb++) {
                uint32_t r0, r1, r2, r3;
                LDMATRIX_X4(r0, r1, r2, r3, sbm + addrB[nb][kh]);
                bf[2 * nb][0] = r0; bf[2 * nb][1] = r1;
                bf[2 * nb + 1][0] = r2; bf[2 * nb + 1][1] = r3;
            }
#pragma unroll
            for (int mi = 0; mi < 4; mi++)
#pragma unroll
                for (int ni = 0; ni < 8; ni++)
                    MMA16816(acc[mi][ni], a[mi][0], a[mi][1], a[mi][2], a[mi][3],
                             bf[ni][0], bf[ni][1]);
        }
    }

    CP_WAIT0();
    __syncthreads();

    // ---- transposed epilogue: slabs of 32 n via smem, coalesced [n][c] writes ----
    // NOTE: slab loop MUST be fully unrolled so acc[][] indexing stays
    // compile-time constant — dynamic indexing demotes acc to local memory
    // and poisons the mainloop (R5/R6 regression root cause).
    float* smf = (float*)smem;                  // [32][132]
    const int s_tensor = m0 >> 9;
    const int cbase = m0 & 511;
#pragma unroll
    for (int slab = 0; slab < 8; ++slab) {
        __syncthreads();
        if ((slab >> 1) == (wn >> 6)) {
            const int nsub = (slab & 1) * 32;
#pragma unroll
            for (int ni4 = 0; ni4 < 4; ni4++) {
                const int ni = (nsub >> 3) + ni4;
                const int nl = ni * 8 + (lane & 3) * 2 - nsub;
                const int r0 = wm + (lane >> 2);
#pragma unroll
                for (int mi = 0; mi < 4; mi++) {
                    const int m = r0 + mi * 16;
                    smf[nl * 132 + m]           = acc[mi][ni][0];
                    smf[(nl + 1) * 132 + m]     = acc[mi][ni][1];
                    smf[nl * 132 + m + 8]       = acc[mi][ni][2];
                    smf[(nl + 1) * 132 + m + 8] = acc[mi][ni][3];
                }
            }
        }
        __syncthreads();
        const int nloc = t >> 3;
        const int c16  = (t & 7) * 16;
        const long ng  = n0 + slab * 32 + nloc;
        float vals[16];
#pragma unroll
        for (int j = 0; j < 16; j++) vals[j] = smf[nloc * 132 + c16 + j];
        if (OUTM == 0) {
            uint32_t hw[8], lw[8];
#pragma unroll
            for (int j = 0; j < 8; j++) {
                float v0 = vals[2 * j], v1 = vals[2 * j + 1];
                __nv_bfloat162 hp = __float22bfloat162_rn(make_float2(v0, v1));
                float r0 = v0 - __bfloat162float(__low2bfloat16(hp));
                float r1 = v1 - __bfloat162float(__high2bfloat16(hp));
                __nv_bfloat162 lp = __float22bfloat162_rn(make_float2(r0, r1));
                hw[j] = *(uint32_t*)&hp;
                lw[j] = *(uint32_t*)&lp;
            }
            uint4* ph = (uint4*)(Ohi + ng * 512 + cbase + c16);
            uint4* pl = (uint4*)(Olo + ng * 512 + cbase + c16);
            ph[0] = make_uint4(hw[0], hw[1], hw[2], hw[3]);
            ph[1] = make_uint4(hw[4], hw[5], hw[6], hw[7]);
            pl[0] = make_uint4(lw[0], lw[1], lw[2], lw[3]);
            pl[1] = make_uint4(lw[4], lw[5], lw[6], lw[7]);
        } else {
            float4* po = (float4*)(Of + (long)s_tensor * QO + ng * 512 + cbase + c16);
#pragma unroll
            for (int j = 0; j < 4; j++)
                po[j] = make_float4(vals[4 * j], vals[4 * j + 1], vals[4 * j + 2], vals[4 * j + 3]);
        }
    }
}

// ---------------- conversion kernels ----------------
__global__ __launch_bounds__(256)
void conv_split(const float* __restrict__ in, __nv_bfloat16* __restrict__ hi,
                __nv_bfloat16* __restrict__ lo, int n)
{
    const int i = blockIdx.x * 256 + threadIdx.x;
    if (i >= n) return;
    const float v = in[i];
    const __nv_bfloat16 h = __float2bfloat16(v);
    hi[i] = h;
    lo[i] = __float2bfloat16(v - __bfloat162float(h));
}

__global__ __launch_bounds__(256)
void conv_wqkv(const float* __restrict__ wq, const float* __restrict__ wk,
               const float* __restrict__ wv,
               __nv_bfloat16* __restrict__ hi, __nv_bfloat16* __restrict__ lo)
{
    const int i = blockIdx.x * 256 + threadIdx.x;
    if (i >= 3 * 512 * 4608) return;
    const int s = i / (512 * 4608);
    const int r = i - s * (512 * 4608);
    const int m = r / 4608;
    const int k = r - m * 4608;
    const int kk = k >> 9;
    const int c = k & 511;
    const float* w = (s == 0) ? wq : ((s == 1) ? wk : wv);
    const float v = w[(m * 512 + c) * 9 + kk];
    const __nv_bfloat16 h = __float2bfloat16(v);
    hi[i] = h;
    lo[i] = __float2bfloat16(v - __bfloat162float(h));
}

__global__ __launch_bounds__(256)
void conv_wc(const float* __restrict__ w,
             __nv_bfloat16* __restrict__ hi, __nv_bfloat16* __restrict__ lo)
{
    const int i = blockIdx.x * 256 + threadIdx.x;
    if (i >= 512 * 4608) return;
    const int m = i / 4608;
    const int k = i - m * 4608;
    const int kk = k >> 9;
    const int c = k & 511;
    const float v = w[(m * 512 + c) * 9 + kk];
    const __nv_bfloat16 h = __float2bfloat16(v);
    hi[i] = h;
    lo[i] = __float2bfloat16(v - __bfloat162float(h));
}

// x [b][2304][196] fp32 -> xT [b*196+p][2304] bf16 hi/lo
__global__ __launch_bounds__(256)
void tconv(const float* __restrict__ in, __nv_bfloat16* __restrict__ hi,
           __nv_bfloat16* __restrict__ lo, int C)
{
    __shared__ float tile[32][33];
    const int b = blockIdx.z;
    const int c0 = blockIdx.y * 32;
    const int p0 = blockIdx.x * 32;
    const int tx = threadIdx.x, ty = threadIdx.y;
    const float* src = in + ((long)b * C + c0) * HWP;
    const int p = p0 + tx;
    for (int i = ty; i < 32; i += 8)
        tile[i][tx] = (p < HWP) ? src[i * HWP + p] : 0.0f;
    __syncthreads();
    for (int i = ty; i < 32; i += 8) {
        const int pp = p0 + i;
        if (pp < HWP) {
            const float v = tile[tx][i];
            const __nv_bfloat16 h = __float2bfloat16(v);
            const long o = ((long)b * HWP + pp) * C + c0 + tx;
            hi[o] = h;
            lo[o] = __float2bfloat16(v - __bfloat162float(h));
        }
    }
}

// ---------------- attention on transposed [n][512] fp32 ----------------
__global__ __launch_bounds__(256)
void attn_scores(const float* __restrict__ Q, const float* __restrict__ Kin, float* __restrict__ A)
{
    const int p = blockIdx.x;
    const int t = threadIdx.x;
    __shared__ float qs[64][33];
    __shared__ float ks[64][33];
    float acc[4][4];
#pragma unroll
    for (int a = 0; a < 4; a++)
#pragma unroll
        for (int b4 = 0; b4 < 4; b4++) acc[a][b4] = 0.0f;
    const int ti = (t & 15) * 4;
    const int tj = (t >> 4) * 4;
    for (int ch = 0; ch < 16; ++ch) {
        const int c0 = ch * 32;
        __syncthreads();
        for (int e = t; e < 64 * 32; e += 256) {
            const int i = e >> 5, c = e & 31;
            qs[i][c] = Q[((long)i * HWP + p) * 512 + c0 + c];
            ks[i][c] = Kin[((long)i * HWP + p) * 512 + c0 + c];
        }
        __syncthreads();
#pragma unroll 8
        for (int c = 0; c < 32; ++c) {
            float qa[4], kb[4];
#pragma unroll
            for (int a = 0; a < 4; a++) qa[a] = qs[ti + a][c];
#pragma unroll
            for (int b4 = 0; b4 < 4; b4++) kb[b4] = ks[tj + b4][c];
#pragma unroll
            for (int a = 0; a < 4; a++)
#pragma unroll
                for (int b4 = 0; b4 < 4; b4++) acc[a][b4] = fmaf(qa[a], kb[b4], acc[a][b4]);
        }
    }
    const float scale = 0.044194173824159216f;
    float* Ab = A + (long)p * 4096;
#pragma unroll
    for (int a = 0; a < 4; a++)
#pragma unroll
        for (int b4 = 0; b4 < 4; b4++)
            Ab[(ti + a) * 64 + tj + b4] = acc[a][b4] * scale;
}

__global__ __launch_bounds__(256)
void softmax_j(float* __restrict__ A)
{
    const int gw   = (blockIdx.x * blockDim.x + threadIdx.x) >> 5;
    const int lane = threadIdx.x & 31;
    if (gw >= HWP * BATCH) return;
    float* row = A + (long)gw * 64;
    float v0 = row[lane];
    float v1 = row[lane + 32];
    float m = fmaxf(v0, v1);
#pragma unroll
    for (int o = 16; o > 0; o >>= 1) m = fmaxf(m, __shfl_xor_sync(0xffffffffu, m, o));
    float e0 = __expf(v0 - m);
    float e1 = __expf(v1 - m);
    float ssum = e0 + e1;
#pragma unroll
    for (int o = 16; o > 0; o >>= 1) ssum += __shfl_xor_sync(0xffffffffu, ssum, o);
    const float inv = 1.0f / ssum;
    row[lane]      = e0 * inv;
    row[lane + 32] = e1 * inv;
}

__global__ __launch_bounds__(256)
void attn_apply(const float* __restrict__ A, const float* __restrict__ V, float* __restrict__ Out)
{
    const int p = blockIdx.x;
    const int t = threadIdx.x;
    __shared__ float as[64][65];
    __shared__ float vs[64][33];
    const float* Ab = A + (long)p * 4096;
    for (int e = t; e < 64 * 64; e += 256) {
        const int i = e >> 6, j = e & 63;
        as[i][j] = Ab[i * 64 + j];
    }
    __syncthreads();
    const int ti = (t & 15) * 4;
    const int tc = (t >> 4) * 2;
    for (int ch = 0; ch < 16; ++ch) {
        const int c0 = ch * 32;
        if (ch) __syncthreads();
        for (int e = t; e < 64 * 32; e += 256) {
            const int j = e >> 5, c = e & 31;
            vs[j][c] = V[((long)j * HWP + p) * 512 + c0 + c];
        }
        __syncthreads();
        float acc[4][2];
#pragma unroll
        for (int a = 0; a < 4; a++) { acc[a][0] = 0.0f; acc[a][1] = 0.0f; }
#pragma unroll 8
        for (int j = 0; j < 64; ++j) {
            float vv0 = vs[j][tc];
            float vv1 = vs[j][tc + 1];
#pragma unroll
            for (int a = 0; a < 4; a++) {
                const float av = as[ti + a][j];
                acc[a][0] = fmaf(av, vv0, acc[a][0]);
                acc[a][1] = fmaf(av, vv1, acc[a][1]);
            }
        }
#pragma unroll
        for (int a = 0; a < 4; a++)
            *(float2*)(Out + ((long)(ti + a) * HWP + p) * 512 + c0 + tc) =
                make_float2(acc[a][0], acc[a][1]);
    }
}

// ---------------- GroupNorm stats (virtT contiguous per batch) ----------------
__global__ __launch_bounds__(256)
void gn_stats(const float* __restrict__ Vt, float* __restrict__ stats)
{
    const int i = blockIdx.x;
    const int t = threadIdx.x;
    float s = 0.0f, s2 = 0.0f;
    const float* row = Vt + (long)i * CHW;
    for (int e = t; e < CHW; e += 256) {
        const float v = row[e];
        s += v;
        s2 = fmaf(v, v, s2);
    }
    __shared__ float sh1[256];
    __shared__ float sh2[256];
    sh1[t] = s; sh2[t] = s2;
    __syncthreads();
    for (int st = 128; st > 0; st >>= 1) {
        if (t < st) { sh1[t] += sh1[t + st]; sh2[t] += sh2[t + st]; }
        __syncthreads();
    }
    if (t == 0) {
        const float inv_n = 1.0f / (float)CHW;
        const float mean = sh1[0] * inv_n;
        const float var  = sh2[0] * inv_n - mean * mean;
        stats[2 * i]     = mean;
        stats[2 * i + 1] = rsqrtf(var + 1e-5f);
    }
}

// fused: normalize + affine + relu + bf16 split -> vT_hi/lo [n][512]
__global__ __launch_bounds__(256)
void gn_split(const float* __restrict__ Vt, const float* __restrict__ stats,
              const float* __restrict__ gamma, const float* __restrict__ beta,
              __nv_bfloat16* __restrict__ hi, __nv_bfloat16* __restrict__ lo)
{
    const long idx = (long)blockIdx.x * 256 + threadIdx.x;
    if (idx >= (long)BATCH * CHW) return;
    const int i = (int)(idx / CHW);
    const int c = (int)(idx & 511);
    const float mean = stats[2 * i];
    const float rstd = stats[2 * i + 1];
    float v = (Vt[idx] - mean) * rstd * gamma[c] + beta[c];
    v = fmaxf(v, 0.0f);
    const __nv_bfloat16 h = __float2bfloat16(v);
    hi[idx] = h;
    lo[idx] = __float2bfloat16(v - __bfloat162float(h));
}

// residual (xrT hi+lo) + coT, avg pool over p, dot with w_pred
__global__ __launch_bounds__(256)
void pool_pred(const __nv_bfloat16* __restrict__ Xh, const __nv_bfloat16* __restrict__ Xl,
               const float* __restrict__ CO, const float* __restrict__ Wp,
               float* __restrict__ out)
{
    const int b = blockIdx.x;
    const int t = threadIdx.x;
    float acc = 0.0f;
    const long base = (long)b * CHW;
    for (int e = t; e < CHW; e += 256) {
        const int c = e & 511;
        const float xv = __bfloat162float(Xh[base + e]) + __bfloat162float(Xl[base + e]);
        acc = fmaf(Wp[c], xv + CO[base + e], acc);
    }
    __shared__ float sh[256];
    sh[t] = acc;
    __syncthreads();
    for (int st = 128; st > 0; st >>= 1) {
        if (t < st) sh[t] += sh[t + st];
        __syncthreads();
    }
    if (t == 0) out[b] = sh[0] * (1.0f / (float)HWP);
}

// ---------------- launcher ----------------
extern "C" void kernel_launch(void* const* d_in, const int* in_sizes, int n_in,
                              void* d_out, int out_size)
{
    const float* x        = (const float*)d_in[0];
    const float* w_reduce = (const float*)d_in[1];
    const float* w_q      = (const float*)d_in[2];
    const float* w_k      = (const float*)d_in[3];
    const float* w_v      = (const float*)d_in[4];
    const float* w_conv   = (const float*)d_in[5];
    const float* gamma    = (const float*)d_in[6];
    const float* beta     = (const float*)d_in[7];
    const float* w_pred   = (const float*)d_in[8];
    float* out = (float*)d_out;

    cudaFuncSetAttribute(gemm_mma<0, 0>, cudaFuncAttributeMaxDynamicSharedMemorySize, GEMM_SMEM);
    cudaFuncSetAttribute(gemm_mma<1, 1>, cudaFuncAttributeMaxDynamicSharedMemorySize, GEMM_SMEM);

    __nv_bfloat16 *xT_hi, *xT_lo, *wr_hi, *wr_lo, *wqkv_hi, *wqkv_lo, *wc_hi, *wc_lo;
    __nv_bfloat16 *xrT_hi, *xrT_lo, *vT_hi, *vT_lo;
    float *qkv, *att, *virt, *co, *stats;
    cudaGetSymbolAddress((void**)&xT_hi,   g_xT_hi);
    cudaGetSymbolAddress((void**)&xT_lo,   g_xT_lo);
    cudaGetSymbolAddress((void**)&wr_hi,   g_wr_hi);
    cudaGetSymbolAddress((void**)&wr_lo,   g_wr_lo);
    cudaGetSymbolAddress((void**)&wqkv_hi, g_wqkv_hi);
    cudaGetSymbolAddress((void**)&wqkv_lo, g_wqkv_lo);
    cudaGetSymbolAddress((void**)&wc_hi,   g_wc_hi);
    cudaGetSymbolAddress((void**)&wc_lo,   g_wc_lo);
    cudaGetSymbolAddress((void**)&xrT_hi,  g_xrT_hi);
    cudaGetSymbolAddress((void**)&xrT_lo,  g_xrT_lo);
    cudaGetSymbolAddress((void**)&qkv,     g_qkv);
    cudaGetSymbolAddress((void**)&att,     g_att);
    cudaGetSymbolAddress((void**)&virt,    g_virt);
    cudaGetSymbolAddress((void**)&vT_hi,   g_vT_hi);
    cudaGetSymbolAddress((void**)&vT_lo,   g_vT_lo);
    cudaGetSymbolAddress((void**)&co,      g_co);
    cudaGetSymbolAddress((void**)&stats,   g_stats);

    // weight conversions
    conv_split<<<(512 * 2304 + 255) / 256, 256>>>(w_reduce, wr_hi, wr_lo, 512 * 2304);
    conv_wqkv<<<(3 * 512 * 4608 + 255) / 256, 256>>>(w_q, w_k, w_v, wqkv_hi, wqkv_lo);
    conv_wc<<<(512 * 4608 + 255) / 256, 256>>>(w_conv, wc_hi, wc_lo);

    // x transpose-convert, then 1x1 reduce -> xrT hi/lo directly
    tconv<<<dim3(7, 72, 64), dim3(32, 8)>>>(x, xT_hi, xT_lo, CIN);
    gemm_mma<0, 0><<<dim3(4, 49), 256, GEMM_SMEM>>>(wr_hi, wr_lo, xT_hi, xT_lo,
                                                    nullptr, xrT_hi, xrT_lo);

    // fused qkv conv GEMM -> qT,kT,vT fp32 [n][512]
    gemm_mma<1, 1><<<dim3(12, 49), 256, GEMM_SMEM>>>(wqkv_hi, wqkv_lo, xrT_hi, xrT_lo,
                                                     qkv, nullptr, nullptr);

    const float* q = qkv;
    const float* k = qkv + (long)QO;
    const float* v = qkv + 2 * (long)QO;

    attn_scores<<<HWP, 256>>>(q, k, att);
    softmax_j<<<(HWP * BATCH * 32 + 255) / 256, 256>>>(att);
    attn_apply<<<HWP, 256>>>(att, v, virt);

    gn_stats<<<BATCH, 256>>>(virt, stats);
    gn_split<<<(int)(((long)BATCH * CHW + 255) / 256), 256>>>(virt, stats, gamma, beta,
                                                              vT_hi, vT_lo);

    // final conv GEMM -> coT fp32 [n][512]
    gemm_mma<1, 1><<<dim3(4, 49), 256, GEMM_SMEM>>>(wc_hi, wc_lo, vT_hi, vT_lo,
                                                    co, nullptr, nullptr);

    pool_pred<<<BATCH, 256>>>(xrT_hi, xrT_lo, co, w_pred, out);
}